// round 6
// baseline (speedup 1.0000x reference)
#include <cuda_runtime.h>
#include <cuda_fp16.h>
#include <math.h>
#include <stdint.h>

// ---------------------------------------------------------------------------
// WindowAttention (Swin): B_=256, N=98, DIM=768, NH=24, HD=32, NW=64
// Phase 1: QKV GEMM, mma.sync fp16, CTA tile 128x256, warp tile 64x64
// Phase 2: tensor-core attention (P 2-split), fused bias table
// ---------------------------------------------------------------------------

#define B_    256
#define NTOK  98
#define DIMC  768
#define NHEAD 24
#define HD    32
#define NWIN  64
#define SCALE 0.17677669529663687f

#define GM (B_ * NTOK)     // 25088
#define GK DIMC            // 768
#define GN (3 * DIMC)      // 2304

// Scratch
__device__ __half g_asp[(size_t)GM * GK];      // x fp16
__device__ __half g_bh[(size_t)GN * GK];       // w fp16
__device__ __half g_qh[B_ * NHEAD * NTOK * HD];
__device__ __half g_kh[B_ * NHEAD * NTOK * HD];
__device__ __half g_vh[B_ * NHEAD * NTOK * HD];
__device__ float  g_bias[NHEAD * NTOK * NTOK]; // fused rel-pos bias [h][r][j]

// ---------------- helpers ---------------------------------------------------

__device__ __forceinline__ uint32_t smem_u32(const void* p) {
    uint32_t a;
    asm("{ .reg .u64 t; cvta.to.shared.u64 t, %1; cvt.u32.u64 %0, t; }" : "=r"(a) : "l"(p));
    return a;
}
#define CP16(dst, src) \
    asm volatile("cp.async.cg.shared.global [%0], [%1], 16;" :: "r"(dst), "l"(src) : "memory")
#define CP_COMMIT() asm volatile("cp.async.commit_group;" ::: "memory")
#define CP_WAIT(n)  asm volatile("cp.async.wait_group %0;" :: "n"(n) : "memory")

__device__ __forceinline__ void ldm_x4(uint32_t& r0, uint32_t& r1, uint32_t& r2,
                                       uint32_t& r3, uint32_t addr) {
    asm volatile("ldmatrix.sync.aligned.m8n8.x4.shared.b16 {%0,%1,%2,%3}, [%4];"
                 : "=r"(r0), "=r"(r1), "=r"(r2), "=r"(r3) : "r"(addr));
}
__device__ __forceinline__ void ldm_x4_t(uint32_t& r0, uint32_t& r1, uint32_t& r2,
                                         uint32_t& r3, uint32_t addr) {
    asm volatile("ldmatrix.sync.aligned.m8n8.x4.trans.shared.b16 {%0,%1,%2,%3}, [%4];"
                 : "=r"(r0), "=r"(r1), "=r"(r2), "=r"(r3) : "r"(addr));
}
__device__ __forceinline__ void mma_f16(float* c, const uint32_t* a, uint32_t b0, uint32_t b1) {
    asm volatile(
        "mma.sync.aligned.m16n8k16.row.col.f32.f16.f16.f32 "
        "{%0,%1,%2,%3}, {%4,%5,%6,%7}, {%8,%9}, {%0,%1,%2,%3};"
        : "+f"(c[0]), "+f"(c[1]), "+f"(c[2]), "+f"(c[3])
        : "r"(a[0]), "r"(a[1]), "r"(a[2]), "r"(a[3]), "r"(b0), "r"(b1));
}
__device__ __forceinline__ uint32_t pack_h2(__half a, __half b) {
    __half2 h = __halves2half2(a, b);
    return *reinterpret_cast<uint32_t*>(&h);
}

// ---------------- prep kernels ----------------------------------------------

__global__ __launch_bounds__(256) void prep_a(const float* __restrict__ x) {
    int i = blockIdx.x * 256 + threadIdx.x;
    if (i < GM * GK) g_asp[i] = __float2half_rn(x[i]);
}
__global__ __launch_bounds__(256) void prep_b(const float* __restrict__ w) {
    int i = blockIdx.x * 256 + threadIdx.x;
    if (i < GN * GK) g_bh[i] = __float2half_rn(w[i]);
}
__global__ __launch_bounds__(256) void prep_bias(
    const float* __restrict__ rel_table, const int* __restrict__ rel_index)
{
    int i = blockIdx.x * 256 + threadIdx.x;
    if (i >= NHEAD * NTOK * NTOK) return;
    int h  = i / (NTOK * NTOK);
    int rj = i - h * (NTOK * NTOK);
    g_bias[i] = __ldg(rel_table + __ldg(rel_index + rj) * NHEAD + h);
}

// ---------------- QKV GEMM (mma.sync fp16) ----------------------------------
// BM=128, BN=256, BK=64. 8 warps (2m x 4n), warp tile 64x64.
// 3-stage cp.async, K=768 (12 chunks). Smem rows 128B, (kc ^ row&7) swizzle.

#define NSTAGE 3
#define CHUNKS 12
#define A_BYTES 16384
#define B_BYTES 32768
#define STAGE_BYTES (A_BYTES + B_BYTES)          // 48KB
#define SMEM_TOTAL (NSTAGE * STAGE_BYTES)        // 144KB

__global__ __launch_bounds__(256) void qkv_mma(const float* __restrict__ bias)
{
    extern __shared__ __align__(128) char smem[];
    const uint32_t sb = smem_u32(smem);

    const int tid  = threadIdx.x;
    const int lane = tid & 31;
    const int wid  = tid >> 5;
    const int wm   = wid & 1;       // 0..1 -> 64 rows
    const int wn   = wid >> 1;      // 0..3 -> 64 cols

    const int m0 = blockIdx.y * 128;
    const int c0 = blockIdx.x * 256;

    const __half* agbase = g_asp + (size_t)m0 * GK;
    const __half* bgbase = g_bh + (size_t)c0 * GK;

    const int sub  = lane >> 3;
    const int lr   = (lane & 7) + ((sub & 1) << 3);
    const int subh = sub >> 1;

    uint32_t a_rowoff[4];
    int      a_rx[4];
#pragma unroll
    for (int i = 0; i < 4; i++) {
        int row = wm * 64 + i * 16 + lr;
        a_rowoff[i] = (uint32_t)row * 128;
        a_rx[i]     = row & 7;
    }
    uint32_t b_rowoff[4];
    int      b_rx[4];
#pragma unroll
    for (int g = 0; g < 4; g++) {
        int row = wn * 64 + g * 16 + lr;
        b_rowoff[g] = (uint32_t)row * 128;
        b_rx[g]     = row & 7;
    }

    float acc[4][8][4];
#pragma unroll
    for (int i = 0; i < 4; i++)
#pragma unroll
        for (int j = 0; j < 8; j++)
#pragma unroll
            for (int q = 0; q < 4; q++) acc[i][j][q] = 0.0f;

    // cp.async: A 1024 chunks (4/thread), B 2048 chunks (8/thread)
#pragma unroll
    for (int c = 0; c < 2; c++) {
        uint32_t aB = sb + c * STAGE_BYTES;
        uint32_t bB = aB + A_BYTES;
#pragma unroll
        for (int l = 0; l < 4; l++) {
            int ci = tid + l * 256;
            int r = ci >> 3, kc = ci & 7;
            CP16(aB + r * 128 + ((kc ^ (r & 7)) << 4),
                 agbase + (size_t)r * GK + c * 64 + kc * 8);
        }
#pragma unroll
        for (int l = 0; l < 8; l++) {
            int ci = tid + l * 256;
            int r = ci >> 3, kc = ci & 7;
            CP16(bB + r * 128 + ((kc ^ (r & 7)) << 4),
                 bgbase + (size_t)r * GK + c * 64 + kc * 8);
        }
        CP_COMMIT();
    }

#pragma unroll 1
    for (int c = 0; c < CHUNKS; c++) {
        if (c + 2 < CHUNKS) {
            int cs = c + 2;
            uint32_t aB = sb + (cs % NSTAGE) * STAGE_BYTES;
            uint32_t bB = aB + A_BYTES;
#pragma unroll
            for (int l = 0; l < 4; l++) {
                int ci = tid + l * 256;
                int r = ci >> 3, kc = ci & 7;
                CP16(aB + r * 128 + ((kc ^ (r & 7)) << 4),
                     agbase + (size_t)r * GK + cs * 64 + kc * 8);
            }
#pragma unroll
            for (int l = 0; l < 8; l++) {
                int ci = tid + l * 256;
                int r = ci >> 3, kc = ci & 7;
                CP16(bB + r * 128 + ((kc ^ (r & 7)) << 4),
                     bgbase + (size_t)r * GK + cs * 64 + kc * 8);
            }
        }
        CP_COMMIT();
        CP_WAIT(2);
        __syncthreads();

        const uint32_t aB = sb + (c % NSTAGE) * STAGE_BYTES;
        const uint32_t bB = aB + A_BYTES;

#pragma unroll
        for (int j = 0; j < 4; j++) {
            uint32_t af[4][4];
#pragma unroll
            for (int i = 0; i < 4; i++) {
                uint32_t addr = aB + a_rowoff[i]
                              + (uint32_t)(((j * 2 + subh) ^ a_rx[i]) << 4);
                ldm_x4(af[i][0], af[i][1], af[i][2], af[i][3], addr);
            }
            uint32_t bf[8][2];
#pragma unroll
            for (int g = 0; g < 4; g++) {
                uint32_t r0, r1, r2, r3;
                uint32_t addr = bB + b_rowoff[g]
                              + (uint32_t)(((j * 2 + subh) ^ b_rx[g]) << 4);
                ldm_x4(r0, r1, r2, r3, addr);
                bf[2 * g][0]     = r0; bf[2 * g][1]     = r2;
                bf[2 * g + 1][0] = r1; bf[2 * g + 1][1] = r3;
            }
#pragma unroll
            for (int i = 0; i < 4; i++)
#pragma unroll
                for (int n = 0; n < 8; n++)
                    mma_f16(acc[i][n], af[i], bf[n][0], bf[n][1]);
        }
        __syncthreads();
    }

    // Epilogue: bias, fold SCALE into Q (single fp16), K/V fp16.
    const int rbase = lane >> 2;
    const int cpair = lane & 3;
#pragma unroll
    for (int i = 0; i < 4; i++) {
#pragma unroll
        for (int half = 0; half < 2; half++) {
            int m = m0 + wm * 64 + i * 16 + rbase + half * 8;
            int b = m / NTOK;
            int tok = m - b * NTOK;
            size_t obase = (size_t)b * NHEAD * NTOK * HD + (size_t)tok * HD;
#pragma unroll
            for (int n = 0; n < 8; n++) {
#pragma unroll
                for (int e = 0; e < 2; e++) {
                    int cc = c0 + wn * 64 + n * 8 + cpair * 2 + e;
                    float v = acc[i][n][half * 2 + e] + __ldg(&bias[cc]);
                    int s3 = cc % 3;
                    int d  = (cc / 3) & 31;
                    int h  = cc / 96;
                    size_t dst = obase + (size_t)h * NTOK * HD + d;
                    if (s3 == 0)      g_qh[dst] = __float2half_rn(v * SCALE);
                    else if (s3 == 1) g_kh[dst] = __float2half_rn(v);
                    else              g_vh[dst] = __float2half_rn(v);
                }
            }
        }
    }
}

// ---------------- tensor-core attention -------------------------------------
// CTA = (h, b). 4 warps. Rows/keys padded 98 -> 112. Row stride 80B in smem.

#define RSTR 40   // halfs per row (80 bytes)

__global__ __launch_bounds__(128) void attn_tc(
    const float* __restrict__ mask,
    float* __restrict__ out)
{
    __shared__ __align__(16) __half sQh[112 * RSTR];
    __shared__ __align__(16) __half sKh[112 * RSTR];
    __shared__ __align__(16) __half sVh[112 * RSTR];

    const int h    = blockIdx.x;
    const int b    = blockIdx.y;
    const int tid  = threadIdx.x;
    const int lane = tid & 31;
    const int w    = tid >> 5;
    const int g    = lane >> 2;   // row group
    const int t    = lane & 3;    // col pair

    const size_t gbase = ((size_t)b * NHEAD + h) * NTOK * HD;
    const uint32_t qhB = smem_u32(sQh);
    const uint32_t khB = smem_u32(sKh);
    const uint32_t vhB = smem_u32(sVh);

    // zero pad rows 98..111
    for (int idx = tid; idx < 14 * 4; idx += 128) {
        int row = 98 + (idx >> 2);
        int q   = idx & 3;
        uint4 z = {0, 0, 0, 0};
        *(uint4*)((char*)sQh + row * 80 + q * 16) = z;
        *(uint4*)((char*)sKh + row * 80 + q * 16) = z;
        *(uint4*)((char*)sVh + row * 80 + q * 16) = z;
    }
    // stage Q/K/V
    for (int idx = tid; idx < 98 * 4; idx += 128) {
        int row = idx >> 2;
        int q   = idx & 3;
        size_t src = gbase + row * 32 + q * 8;
        uint32_t doff = row * 80 + q * 16;
        CP16(qhB + doff, g_qh + src);
        CP16(khB + doff, g_kh + src);
        CP16(vhB + doff, g_vh + src);
    }
    CP_COMMIT();
    CP_WAIT(0);
    __syncthreads();

    const float* maskw = mask + (size_t)(b & (NWIN - 1)) * NTOK * NTOK;
    const float* biash = g_bias + (size_t)h * NTOK * NTOK;

#pragma unroll 1
    for (int mi = 0; mi < 2; mi++) {
        int mt = w + mi * 4;
        if (mt > 6) break;
        const int r0 = mt * 16;

        // ---- Q fragments (2 k16 tiles) --------------------------------------
        uint32_t qh[2][4];
        {
            int qrow = r0 + (lane & 7) + (((lane >> 3) & 1) << 3);
            int qcol = ((lane >> 4) << 3);
#pragma unroll
            for (int kt = 0; kt < 2; kt++) {
                uint32_t off = (uint32_t)qrow * 80 + (uint32_t)(kt * 16 + qcol) * 2;
                ldm_x4(qh[kt][0], qh[kt][1], qh[kt][2], qh[kt][3], qhB + off);
            }
        }

        // ---- S = Q K^T ------------------------------------------------------
        float sc[14][4];
#pragma unroll
        for (int i = 0; i < 14; i++)
#pragma unroll
            for (int q = 0; q < 4; q++) sc[i][q] = 0.0f;

        {
            int krow = (lane & 7) + ((lane >> 4) << 3);
            int kcol = ((lane >> 3) & 1) << 3;
#pragma unroll
            for (int nt2 = 0; nt2 < 7; nt2++) {
                int j0 = nt2 * 16;
                uint32_t k0[4], k1[4];
                uint32_t roff = (uint32_t)(j0 + krow) * 80;
                ldm_x4(k0[0], k0[1], k0[2], k0[3], khB + roff + (uint32_t)(kcol) * 2);
                ldm_x4(k1[0], k1[1], k1[2], k1[3], khB + roff + (uint32_t)(16 + kcol) * 2);
                float* aA = sc[2 * nt2];
                float* aB = sc[2 * nt2 + 1];
                mma_f16(aA, qh[0], k0[0], k0[1]);
                mma_f16(aA, qh[1], k1[0], k1[1]);
                mma_f16(aB, qh[0], k0[2], k0[3]);
                mma_f16(aB, qh[1], k1[2], k1[3]);
            }
        }

        // ---- bias + mask + softmax (registers only) -------------------------
#pragma unroll
        for (int h2 = 0; h2 < 2; h2++) {
            int row = r0 + g + h2 * 8;
            float mx = -1e30f;
            bool rok = (row < NTOK);
#pragma unroll
            for (int i = 0; i < 14; i++) {
                int jc = 8 * i + 2 * t;
                float s0, s1;
                if (rok && jc < NTOK) {
                    float2 mk = *(const float2*)(maskw + row * NTOK + jc);
                    float2 bi = *(const float2*)(biash + row * NTOK + jc);
                    s0 = sc[i][h2 * 2]     + mk.x + bi.x;
                    s1 = sc[i][h2 * 2 + 1] + mk.y + bi.y;
                } else {
                    s0 = -1e30f; s1 = -1e30f;
                }
                sc[i][h2 * 2]     = s0;
                sc[i][h2 * 2 + 1] = s1;
                mx = fmaxf(mx, fmaxf(s0, s1));
            }
            mx = fmaxf(mx, __shfl_xor_sync(0xffffffffu, mx, 1));
            mx = fmaxf(mx, __shfl_xor_sync(0xffffffffu, mx, 2));
            float sum = 0.0f;
#pragma unroll
            for (int i = 0; i < 14; i++) {
                float p0 = __expf(sc[i][h2 * 2]     - mx);
                float p1 = __expf(sc[i][h2 * 2 + 1] - mx);
                sc[i][h2 * 2]     = p0;
                sc[i][h2 * 2 + 1] = p1;
                sum += p0 + p1;
            }
            sum += __shfl_xor_sync(0xffffffffu, sum, 1);
            sum += __shfl_xor_sync(0xffffffffu, sum, 2);
            float inv = 1.0f / sum;
#pragma unroll
            for (int i = 0; i < 14; i++) {
                sc[i][h2 * 2]     *= inv;
                sc[i][h2 * 2 + 1] *= inv;
            }
        }

        // ---- O = P V (P split hi/lo for accuracy) ---------------------------
        float o[4][4];
#pragma unroll
        for (int n = 0; n < 4; n++)
#pragma unroll
            for (int q = 0; q < 4; q++) o[n][q] = 0.0f;

        {
            int vrow = (lane & 7) + (((lane >> 3) & 1) << 3);
            int vcol = (lane >> 4) << 3;
#pragma unroll
            for (int kk = 0; kk < 7; kk++) {
                uint32_t ph[4], pl[4];
                {
                    float e0 = sc[2 * kk][0],     e1 = sc[2 * kk][1];
                    float e2 = sc[2 * kk][2],     e3 = sc[2 * kk][3];
                    float e4 = sc[2 * kk + 1][0], e5 = sc[2 * kk + 1][1];
                    float e6 = sc[2 * kk + 1][2], e7 = sc[2 * kk + 1][3];
                    __half h0 = __float2half_rn(e0), h1 = __float2half_rn(e1);
                    __half h2 = __float2half_rn(e2), h3 = __float2half_rn(e3);
                    __half h4 = __float2half_rn(e4), h5 = __float2half_rn(e5);
                    __half h6 = __float2half_rn(e6), h7 = __float2half_rn(e7);
                    ph[0] = pack_h2(h0, h1);
                    ph[1] = pack_h2(h2, h3);
                    ph[2] = pack_h2(h4, h5);
                    ph[3] = pack_h2(h6, h7);
                    pl[0] = pack_h2(__float2half_rn(e0 - __half2float(h0)),
                                    __float2half_rn(e1 - __half2float(h1)));
                    pl[1] = pack_h2(__float2half_rn(e2 - __half2float(h2)),
                                    __float2half_rn(e3 - __half2float(h3)));
                    pl[2] = pack_h2(__float2half_rn(e4 - __half2float(h4)),
                                    __float2half_rn(e5 - __half2float(h5)));
                    pl[3] = pack_h2(__float2half_rn(e6 - __half2float(h6)),
                                    __float2half_rn(e7 - __half2float(h7)));
                }
                int j0 = kk * 16;
                uint32_t v0[4], v16[4];
                uint32_t roff = (uint32_t)(j0 + vrow) * 80;
                ldm_x4_t(v0[0], v0[1], v0[2], v0[3],  vhB + roff + (uint32_t)vcol * 2);
                ldm_x4_t(v16[0], v16[1], v16[2], v16[3],
                         vhB + roff + (uint32_t)(16 + vcol) * 2);
                mma_f16(o[0], ph, v0[0], v0[1]);
                mma_f16(o[1], ph, v0[2], v0[3]);
                mma_f16(o[2], ph, v16[0], v16[1]);
                mma_f16(o[3], ph, v16[2], v16[3]);
                mma_f16(o[0], pl, v0[0], v0[1]);
                mma_f16(o[1], pl, v0[2], v0[3]);
                mma_f16(o[2], pl, v16[0], v16[1]);
                mma_f16(o[3], pl, v16[2], v16[3]);
            }
        }

        // ---- store ----------------------------------------------------------
        {
            int rowA = r0 + g;
            int rowB = rowA + 8;
            if (rowA < NTOK) {
                float* dst = out + ((size_t)b * NTOK + rowA) * DIMC + h * HD;
#pragma unroll
                for (int n = 0; n < 4; n++) {
                    float2 v = {o[n][0], o[n][1]};
                    *(float2*)(dst + n * 8 + 2 * t) = v;
                }
            }
            if (rowB < NTOK) {
                float* dst = out + ((size_t)b * NTOK + rowB) * DIMC + h * HD;
#pragma unroll
                for (int n = 0; n < 4; n++) {
                    float2 v = {o[n][2], o[n][3]};
                    *(float2*)(dst + n * 8 + 2 * t) = v;
                }
            }
        }
    }
}

// ------------------------- launch ------------------------------------------

extern "C" void kernel_launch(void* const* d_in, const int* in_sizes, int n_in,
                              void* d_out, int out_size)
{
    const float* x         = (const float*)d_in[0];
    const float* mask      = (const float*)d_in[1];
    const float* qkv_w     = (const float*)d_in[2];
    const float* qkv_b     = (const float*)d_in[3];
    const float* rel_table = (const float*)d_in[4];
    const int*   rel_index = (const int*)  d_in[5];
    float* out = (float*)d_out;

    prep_a<<<(GM * GK + 255) / 256, 256>>>(x);
    prep_b<<<(GN * GK + 255) / 256, 256>>>(qkv_w);
    prep_bias<<<(NHEAD * NTOK * NTOK + 255) / 256, 256>>>(rel_table, rel_index);

    cudaFuncSetAttribute(qkv_mma, cudaFuncAttributeMaxDynamicSharedMemorySize,
                         SMEM_TOTAL);
    dim3 g1(GN / 256, GM / 128);    // (9, 196)
    qkv_mma<<<g1, 256, SMEM_TOTAL>>>(qkv_b);

    dim3 g2(NHEAD, B_);             // (24, 256)
    attn_tc<<<g2, 128>>>(mask, out);
}

// round 7
// speedup vs baseline: 1.2141x; 1.2141x over previous
#include <cuda_runtime.h>
#include <cuda_fp16.h>
#include <math.h>
#include <stdint.h>

// ---------------------------------------------------------------------------
// WindowAttention (Swin): B_=256, N=98, DIM=768, NH=24, HD=32, NW=64
// Phase 1: QKV GEMM, mma.sync fp16. CTA 128x128, 4 warps (64x64 each),
//          3-stage cp.async, 2 CTAs/SM.
// Phase 2: tensor-core attention (P 2-split), fused bias table
// ---------------------------------------------------------------------------

#define B_    256
#define NTOK  98
#define DIMC  768
#define NHEAD 24
#define HD    32
#define NWIN  64
#define SCALE 0.17677669529663687f

#define GM (B_ * NTOK)     // 25088
#define GK DIMC            // 768
#define GN (3 * DIMC)      // 2304

// Scratch
__device__ __half g_asp[(size_t)GM * GK];      // x fp16
__device__ __half g_bh[(size_t)GN * GK];       // w fp16
__device__ __half g_qh[B_ * NHEAD * NTOK * HD];
__device__ __half g_kh[B_ * NHEAD * NTOK * HD];
__device__ __half g_vh[B_ * NHEAD * NTOK * HD];
__device__ float  g_bias[NHEAD * NTOK * NTOK]; // fused rel-pos bias [h][r][j]

// ---------------- helpers ---------------------------------------------------

__device__ __forceinline__ uint32_t smem_u32(const void* p) {
    uint32_t a;
    asm("{ .reg .u64 t; cvta.to.shared.u64 t, %1; cvt.u32.u64 %0, t; }" : "=r"(a) : "l"(p));
    return a;
}
#define CP16(dst, src) \
    asm volatile("cp.async.cg.shared.global [%0], [%1], 16;" :: "r"(dst), "l"(src) : "memory")
#define CP_COMMIT() asm volatile("cp.async.commit_group;" ::: "memory")
#define CP_WAIT(n)  asm volatile("cp.async.wait_group %0;" :: "n"(n) : "memory")

__device__ __forceinline__ void ldm_x4(uint32_t& r0, uint32_t& r1, uint32_t& r2,
                                       uint32_t& r3, uint32_t addr) {
    asm volatile("ldmatrix.sync.aligned.m8n8.x4.shared.b16 {%0,%1,%2,%3}, [%4];"
                 : "=r"(r0), "=r"(r1), "=r"(r2), "=r"(r3) : "r"(addr));
}
__device__ __forceinline__ void ldm_x4_t(uint32_t& r0, uint32_t& r1, uint32_t& r2,
                                         uint32_t& r3, uint32_t addr) {
    asm volatile("ldmatrix.sync.aligned.m8n8.x4.trans.shared.b16 {%0,%1,%2,%3}, [%4];"
                 : "=r"(r0), "=r"(r1), "=r"(r2), "=r"(r3) : "r"(addr));
}
__device__ __forceinline__ void mma_f16(float* c, const uint32_t* a, uint32_t b0, uint32_t b1) {
    asm volatile(
        "mma.sync.aligned.m16n8k16.row.col.f32.f16.f16.f32 "
        "{%0,%1,%2,%3}, {%4,%5,%6,%7}, {%8,%9}, {%0,%1,%2,%3};"
        : "+f"(c[0]), "+f"(c[1]), "+f"(c[2]), "+f"(c[3])
        : "r"(a[0]), "r"(a[1]), "r"(a[2]), "r"(a[3]), "r"(b0), "r"(b1));
}
__device__ __forceinline__ uint32_t pack_h2(__half a, __half b) {
    __half2 h = __halves2half2(a, b);
    return *reinterpret_cast<uint32_t*>(&h);
}

// ---------------- prep kernels ----------------------------------------------

__global__ __launch_bounds__(256) void prep_a(const float* __restrict__ x) {
    int i = blockIdx.x * 256 + threadIdx.x;
    if (i < GM * GK) g_asp[i] = __float2half_rn(x[i]);
}
__global__ __launch_bounds__(256) void prep_b(const float* __restrict__ w) {
    int i = blockIdx.x * 256 + threadIdx.x;
    if (i < GN * GK) g_bh[i] = __float2half_rn(w[i]);
}
__global__ __launch_bounds__(256) void prep_bias(
    const float* __restrict__ rel_table, const int* __restrict__ rel_index)
{
    int i = blockIdx.x * 256 + threadIdx.x;
    if (i >= NHEAD * NTOK * NTOK) return;
    int h  = i / (NTOK * NTOK);
    int rj = i - h * (NTOK * NTOK);
    g_bias[i] = __ldg(rel_table + __ldg(rel_index + rj) * NHEAD + h);
}

// ---------------- QKV GEMM (mma.sync fp16) ----------------------------------
// BM=128, BN=128, BK=64. 4 warps (2m x 2n), warp tile 64x64.
// 3-stage cp.async, K=768 (12 chunks). Smem rows 128B, (kc ^ row&7) swizzle.

#define NSTAGE 3
#define CHUNKS 12
#define A_BYTES 16384
#define BB_BYTES 16384
#define STAGE_BYTES (A_BYTES + BB_BYTES)         // 32KB
#define SMEM_TOTAL (NSTAGE * STAGE_BYTES)        // 96KB

__global__ __launch_bounds__(128, 2) void qkv_mma(const float* __restrict__ bias)
{
    extern __shared__ __align__(128) char smem[];
    const uint32_t sb = smem_u32(smem);

    const int tid  = threadIdx.x;
    const int lane = tid & 31;
    const int wid  = tid >> 5;
    const int wm   = wid & 1;        // 0..1 -> 64 rows
    const int wn   = wid >> 1;       // 0..1 -> 64 cols

    const int m0 = blockIdx.y * 128;
    const int c0 = blockIdx.x * 128;

    const __half* agbase = g_asp + (size_t)m0 * GK;
    const __half* bgbase = g_bh + (size_t)c0 * GK;

    const int sub  = lane >> 3;
    const int lr   = (lane & 7) + ((sub & 1) << 3);
    const int subh = sub >> 1;

    uint32_t a_rowoff[4];
    int      a_rx[4];
#pragma unroll
    for (int i = 0; i < 4; i++) {
        int row = wm * 64 + i * 16 + lr;
        a_rowoff[i] = (uint32_t)row * 128;
        a_rx[i]     = row & 7;
    }
    uint32_t b_rowoff[4];
    int      b_rx[4];
#pragma unroll
    for (int g = 0; g < 4; g++) {
        int row = wn * 64 + g * 16 + lr;
        b_rowoff[g] = (uint32_t)row * 128;
        b_rx[g]     = row & 7;
    }

    float acc[4][8][4];
#pragma unroll
    for (int i = 0; i < 4; i++)
#pragma unroll
        for (int j = 0; j < 8; j++)
#pragma unroll
            for (int q = 0; q < 4; q++) acc[i][j][q] = 0.0f;

    // cp.async: A 1024 16B-chunks (8/thread), B 1024 (8/thread)
#pragma unroll
    for (int c = 0; c < 2; c++) {
        uint32_t aB = sb + c * STAGE_BYTES;
        uint32_t bB = aB + A_BYTES;
#pragma unroll
        for (int l = 0; l < 8; l++) {
            int ci = tid + l * 128;
            int r = ci >> 3, kc = ci & 7;
            CP16(aB + r * 128 + ((kc ^ (r & 7)) << 4),
                 agbase + (size_t)r * GK + c * 64 + kc * 8);
            CP16(bB + r * 128 + ((kc ^ (r & 7)) << 4),
                 bgbase + (size_t)r * GK + c * 64 + kc * 8);
        }
        CP_COMMIT();
    }

#pragma unroll 1
    for (int c = 0; c < CHUNKS; c++) {
        if (c + 2 < CHUNKS) {
            int cs = c + 2;
            uint32_t aB = sb + (cs % NSTAGE) * STAGE_BYTES;
            uint32_t bB = aB + A_BYTES;
#pragma unroll
            for (int l = 0; l < 8; l++) {
                int ci = tid + l * 128;
                int r = ci >> 3, kc = ci & 7;
                CP16(aB + r * 128 + ((kc ^ (r & 7)) << 4),
                     agbase + (size_t)r * GK + cs * 64 + kc * 8);
                CP16(bB + r * 128 + ((kc ^ (r & 7)) << 4),
                     bgbase + (size_t)r * GK + cs * 64 + kc * 8);
            }
        }
        CP_COMMIT();
        CP_WAIT(2);
        __syncthreads();

        const uint32_t aB = sb + (c % NSTAGE) * STAGE_BYTES;
        const uint32_t bB = aB + A_BYTES;

#pragma unroll
        for (int j = 0; j < 4; j++) {
            uint32_t af[4][4];
#pragma unroll
            for (int i = 0; i < 4; i++) {
                uint32_t addr = aB + a_rowoff[i]
                              + (uint32_t)(((j * 2 + subh) ^ a_rx[i]) << 4);
                ldm_x4(af[i][0], af[i][1], af[i][2], af[i][3], addr);
            }
            uint32_t bf[8][2];
#pragma unroll
            for (int g = 0; g < 4; g++) {
                uint32_t r0, r1, r2, r3;
                uint32_t addr = bB + b_rowoff[g]
                              + (uint32_t)(((j * 2 + subh) ^ b_rx[g]) << 4);
                ldm_x4(r0, r1, r2, r3, addr);
                bf[2 * g][0]     = r0; bf[2 * g][1]     = r2;
                bf[2 * g + 1][0] = r1; bf[2 * g + 1][1] = r3;
            }
#pragma unroll
            for (int i = 0; i < 4; i++)
#pragma unroll
                for (int n = 0; n < 8; n++)
                    mma_f16(acc[i][n], af[i], bf[n][0], bf[n][1]);
        }
        __syncthreads();
    }

    // Epilogue: bias, fold SCALE into Q (single fp16), K/V fp16.
    const int rbase = lane >> 2;
    const int cpair = lane & 3;
#pragma unroll
    for (int i = 0; i < 4; i++) {
#pragma unroll
        for (int half = 0; half < 2; half++) {
            int m = m0 + wm * 64 + i * 16 + rbase + half * 8;
            int b = m / NTOK;
            int tok = m - b * NTOK;
            size_t obase = (size_t)b * NHEAD * NTOK * HD + (size_t)tok * HD;
#pragma unroll
            for (int n = 0; n < 8; n++) {
#pragma unroll
                for (int e = 0; e < 2; e++) {
                    int cc = c0 + wn * 64 + n * 8 + cpair * 2 + e;
                    float v = acc[i][n][half * 2 + e] + __ldg(&bias[cc]);
                    int s3 = cc % 3;
                    int d  = (cc / 3) & 31;
                    int h  = cc / 96;
                    size_t dst = obase + (size_t)h * NTOK * HD + d;
                    if (s3 == 0)      g_qh[dst] = __float2half_rn(v * SCALE);
                    else if (s3 == 1) g_kh[dst] = __float2half_rn(v);
                    else              g_vh[dst] = __float2half_rn(v);
                }
            }
        }
    }
}

// ---------------- tensor-core attention -------------------------------------
// CTA = (h, b). 4 warps. Rows/keys padded 98 -> 112. Row stride 80B in smem.

#define RSTR 40   // halfs per row (80 bytes)

__global__ __launch_bounds__(128) void attn_tc(
    const float* __restrict__ mask,
    float* __restrict__ out)
{
    __shared__ __align__(16) __half sQh[112 * RSTR];
    __shared__ __align__(16) __half sKh[112 * RSTR];
    __shared__ __align__(16) __half sVh[112 * RSTR];

    const int h    = blockIdx.x;
    const int b    = blockIdx.y;
    const int tid  = threadIdx.x;
    const int lane = tid & 31;
    const int w    = tid >> 5;
    const int g    = lane >> 2;   // row group
    const int t    = lane & 3;    // col pair

    const size_t gbase = ((size_t)b * NHEAD + h) * NTOK * HD;
    const uint32_t qhB = smem_u32(sQh);
    const uint32_t khB = smem_u32(sKh);
    const uint32_t vhB = smem_u32(sVh);

    // zero pad rows 98..111
    for (int idx = tid; idx < 14 * 4; idx += 128) {
        int row = 98 + (idx >> 2);
        int q   = idx & 3;
        uint4 z = {0, 0, 0, 0};
        *(uint4*)((char*)sQh + row * 80 + q * 16) = z;
        *(uint4*)((char*)sKh + row * 80 + q * 16) = z;
        *(uint4*)((char*)sVh + row * 80 + q * 16) = z;
    }
    // stage Q/K/V
    for (int idx = tid; idx < 98 * 4; idx += 128) {
        int row = idx >> 2;
        int q   = idx & 3;
        size_t src = gbase + row * 32 + q * 8;
        uint32_t doff = row * 80 + q * 16;
        CP16(qhB + doff, g_qh + src);
        CP16(khB + doff, g_kh + src);
        CP16(vhB + doff, g_vh + src);
    }
    CP_COMMIT();
    CP_WAIT(0);
    __syncthreads();

    const float* maskw = mask + (size_t)(b & (NWIN - 1)) * NTOK * NTOK;
    const float* biash = g_bias + (size_t)h * NTOK * NTOK;

#pragma unroll 1
    for (int mi = 0; mi < 2; mi++) {
        int mt = w + mi * 4;
        if (mt > 6) break;
        const int r0 = mt * 16;

        // ---- Q fragments (2 k16 tiles) --------------------------------------
        uint32_t qh[2][4];
        {
            int qrow = r0 + (lane & 7) + (((lane >> 3) & 1) << 3);
            int qcol = ((lane >> 4) << 3);
#pragma unroll
            for (int kt = 0; kt < 2; kt++) {
                uint32_t off = (uint32_t)qrow * 80 + (uint32_t)(kt * 16 + qcol) * 2;
                ldm_x4(qh[kt][0], qh[kt][1], qh[kt][2], qh[kt][3], qhB + off);
            }
        }

        // ---- S = Q K^T ------------------------------------------------------
        float sc[14][4];
#pragma unroll
        for (int i = 0; i < 14; i++)
#pragma unroll
            for (int q = 0; q < 4; q++) sc[i][q] = 0.0f;

        {
            int krow = (lane & 7) + ((lane >> 4) << 3);
            int kcol = ((lane >> 3) & 1) << 3;
#pragma unroll
            for (int nt2 = 0; nt2 < 7; nt2++) {
                int j0 = nt2 * 16;
                uint32_t k0[4], k1[4];
                uint32_t roff = (uint32_t)(j0 + krow) * 80;
                ldm_x4(k0[0], k0[1], k0[2], k0[3], khB + roff + (uint32_t)(kcol) * 2);
                ldm_x4(k1[0], k1[1], k1[2], k1[3], khB + roff + (uint32_t)(16 + kcol) * 2);
                float* aA = sc[2 * nt2];
                float* aB = sc[2 * nt2 + 1];
                mma_f16(aA, qh[0], k0[0], k0[1]);
                mma_f16(aA, qh[1], k1[0], k1[1]);
                mma_f16(aB, qh[0], k0[2], k0[3]);
                mma_f16(aB, qh[1], k1[2], k1[3]);
            }
        }

        // ---- bias + mask + softmax (registers only) -------------------------
#pragma unroll
        for (int h2 = 0; h2 < 2; h2++) {
            int row = r0 + g + h2 * 8;
            float mx = -1e30f;
            bool rok = (row < NTOK);
#pragma unroll
            for (int i = 0; i < 14; i++) {
                int jc = 8 * i + 2 * t;
                float s0, s1;
                if (rok && jc < NTOK) {
                    float2 mk = *(const float2*)(maskw + row * NTOK + jc);
                    float2 bi = *(const float2*)(biash + row * NTOK + jc);
                    s0 = sc[i][h2 * 2]     + mk.x + bi.x;
                    s1 = sc[i][h2 * 2 + 1] + mk.y + bi.y;
                } else {
                    s0 = -1e30f; s1 = -1e30f;
                }
                sc[i][h2 * 2]     = s0;
                sc[i][h2 * 2 + 1] = s1;
                mx = fmaxf(mx, fmaxf(s0, s1));
            }
            mx = fmaxf(mx, __shfl_xor_sync(0xffffffffu, mx, 1));
            mx = fmaxf(mx, __shfl_xor_sync(0xffffffffu, mx, 2));
            float sum = 0.0f;
#pragma unroll
            for (int i = 0; i < 14; i++) {
                float p0 = __expf(sc[i][h2 * 2]     - mx);
                float p1 = __expf(sc[i][h2 * 2 + 1] - mx);
                sc[i][h2 * 2]     = p0;
                sc[i][h2 * 2 + 1] = p1;
                sum += p0 + p1;
            }
            sum += __shfl_xor_sync(0xffffffffu, sum, 1);
            sum += __shfl_xor_sync(0xffffffffu, sum, 2);
            float inv = 1.0f / sum;
#pragma unroll
            for (int i = 0; i < 14; i++) {
                sc[i][h2 * 2]     *= inv;
                sc[i][h2 * 2 + 1] *= inv;
            }
        }

        // ---- O = P V (P split hi/lo for accuracy) ---------------------------
        float o[4][4];
#pragma unroll
        for (int n = 0; n < 4; n++)
#pragma unroll
            for (int q = 0; q < 4; q++) o[n][q] = 0.0f;

        {
            int vrow = (lane & 7) + (((lane >> 3) & 1) << 3);
            int vcol = (lane >> 4) << 3;
#pragma unroll
            for (int kk = 0; kk < 7; kk++) {
                uint32_t ph[4], pl[4];
                {
                    float e0 = sc[2 * kk][0],     e1 = sc[2 * kk][1];
                    float e2 = sc[2 * kk][2],     e3 = sc[2 * kk][3];
                    float e4 = sc[2 * kk + 1][0], e5 = sc[2 * kk + 1][1];
                    float e6 = sc[2 * kk + 1][2], e7 = sc[2 * kk + 1][3];
                    __half h0 = __float2half_rn(e0), h1 = __float2half_rn(e1);
                    __half h2 = __float2half_rn(e2), h3 = __float2half_rn(e3);
                    __half h4 = __float2half_rn(e4), h5 = __float2half_rn(e5);
                    __half h6 = __float2half_rn(e6), h7 = __float2half_rn(e7);
                    ph[0] = pack_h2(h0, h1);
                    ph[1] = pack_h2(h2, h3);
                    ph[2] = pack_h2(h4, h5);
                    ph[3] = pack_h2(h6, h7);
                    pl[0] = pack_h2(__float2half_rn(e0 - __half2float(h0)),
                                    __float2half_rn(e1 - __half2float(h1)));
                    pl[1] = pack_h2(__float2half_rn(e2 - __half2float(h2)),
                                    __float2half_rn(e3 - __half2float(h3)));
                    pl[2] = pack_h2(__float2half_rn(e4 - __half2float(h4)),
                                    __float2half_rn(e5 - __half2float(h5)));
                    pl[3] = pack_h2(__float2half_rn(e6 - __half2float(h6)),
                                    __float2half_rn(e7 - __half2float(h7)));
                }
                int j0 = kk * 16;
                uint32_t v0[4], v16[4];
                uint32_t roff = (uint32_t)(j0 + vrow) * 80;
                ldm_x4_t(v0[0], v0[1], v0[2], v0[3],  vhB + roff + (uint32_t)vcol * 2);
                ldm_x4_t(v16[0], v16[1], v16[2], v16[3],
                         vhB + roff + (uint32_t)(16 + vcol) * 2);
                mma_f16(o[0], ph, v0[0], v0[1]);
                mma_f16(o[1], ph, v0[2], v0[3]);
                mma_f16(o[2], ph, v16[0], v16[1]);
                mma_f16(o[3], ph, v16[2], v16[3]);
                mma_f16(o[0], pl, v0[0], v0[1]);
                mma_f16(o[1], pl, v0[2], v0[3]);
                mma_f16(o[2], pl, v16[0], v16[1]);
                mma_f16(o[3], pl, v16[2], v16[3]);
            }
        }

        // ---- store ----------------------------------------------------------
        {
            int rowA = r0 + g;
            int rowB = rowA + 8;
            if (rowA < NTOK) {
                float* dst = out + ((size_t)b * NTOK + rowA) * DIMC + h * HD;
#pragma unroll
                for (int n = 0; n < 4; n++) {
                    float2 v = {o[n][0], o[n][1]};
                    *(float2*)(dst + n * 8 + 2 * t) = v;
                }
            }
            if (rowB < NTOK) {
                float* dst = out + ((size_t)b * NTOK + rowB) * DIMC + h * HD;
#pragma unroll
                for (int n = 0; n < 4; n++) {
                    float2 v = {o[n][2], o[n][3]};
                    *(float2*)(dst + n * 8 + 2 * t) = v;
                }
            }
        }
    }
}

// ------------------------- launch ------------------------------------------

extern "C" void kernel_launch(void* const* d_in, const int* in_sizes, int n_in,
                              void* d_out, int out_size)
{
    const float* x         = (const float*)d_in[0];
    const float* mask      = (const float*)d_in[1];
    const float* qkv_w     = (const float*)d_in[2];
    const float* qkv_b     = (const float*)d_in[3];
    const float* rel_table = (const float*)d_in[4];
    const int*   rel_index = (const int*)  d_in[5];
    float* out = (float*)d_out;

    prep_a<<<(GM * GK + 255) / 256, 256>>>(x);
    prep_b<<<(GN * GK + 255) / 256, 256>>>(qkv_w);
    prep_bias<<<(NHEAD * NTOK * NTOK + 255) / 256, 256>>>(rel_table, rel_index);

    cudaFuncSetAttribute(qkv_mma, cudaFuncAttributeMaxDynamicSharedMemorySize,
                         SMEM_TOTAL);
    dim3 g1(GN / 128, GM / 128);    // (18, 196)
    qkv_mma<<<g1, 128, SMEM_TOTAL>>>(qkv_b);

    dim3 g2(NHEAD, B_);             // (24, 256)
    attn_tc<<<g2, 128>>>(mask, out);
}

// round 8
// speedup vs baseline: 1.3825x; 1.1387x over previous
#include <cuda_runtime.h>
#include <cuda_fp16.h>
#include <math.h>
#include <stdint.h>

// ---------------------------------------------------------------------------
// WindowAttention (Swin): B_=256, N=98, DIM=768, NH=24, HD=32, NW=64
// Phase 1: QKV GEMM, mma.sync fp16. CTA 128x96 (one head), 4 warps (64x48),
//          2-stage cp.async, 3 CTAs/SM.
// Phase 2: tensor-core attention (P 2-split), fused bias table
// ---------------------------------------------------------------------------

#define B_    256
#define NTOK  98
#define DIMC  768
#define NHEAD 24
#define HD    32
#define NWIN  64
#define SCALE 0.17677669529663687f

#define GM (B_ * NTOK)     // 25088
#define GK DIMC            // 768
#define GN (3 * DIMC)      // 2304

// Scratch
__device__ __half g_asp[(size_t)GM * GK];      // x fp16
__device__ __half g_bh[(size_t)GN * GK];       // w fp16
__device__ __half g_qh[B_ * NHEAD * NTOK * HD];
__device__ __half g_kh[B_ * NHEAD * NTOK * HD];
__device__ __half g_vh[B_ * NHEAD * NTOK * HD];
__device__ float  g_bias[NHEAD * NTOK * NTOK]; // fused rel-pos bias [h][r][j]

// ---------------- helpers ---------------------------------------------------

__device__ __forceinline__ uint32_t smem_u32(const void* p) {
    uint32_t a;
    asm("{ .reg .u64 t; cvta.to.shared.u64 t, %1; cvt.u32.u64 %0, t; }" : "=r"(a) : "l"(p));
    return a;
}
#define CP16(dst, src) \
    asm volatile("cp.async.cg.shared.global [%0], [%1], 16;" :: "r"(dst), "l"(src) : "memory")
#define CP_COMMIT() asm volatile("cp.async.commit_group;" ::: "memory")
#define CP_WAIT(n)  asm volatile("cp.async.wait_group %0;" :: "n"(n) : "memory")

__device__ __forceinline__ void ldm_x4(uint32_t& r0, uint32_t& r1, uint32_t& r2,
                                       uint32_t& r3, uint32_t addr) {
    asm volatile("ldmatrix.sync.aligned.m8n8.x4.shared.b16 {%0,%1,%2,%3}, [%4];"
                 : "=r"(r0), "=r"(r1), "=r"(r2), "=r"(r3) : "r"(addr));
}
__device__ __forceinline__ void ldm_x4_t(uint32_t& r0, uint32_t& r1, uint32_t& r2,
                                         uint32_t& r3, uint32_t addr) {
    asm volatile("ldmatrix.sync.aligned.m8n8.x4.trans.shared.b16 {%0,%1,%2,%3}, [%4];"
                 : "=r"(r0), "=r"(r1), "=r"(r2), "=r"(r3) : "r"(addr));
}
__device__ __forceinline__ void mma_f16(float* c, const uint32_t* a, uint32_t b0, uint32_t b1) {
    asm volatile(
        "mma.sync.aligned.m16n8k16.row.col.f32.f16.f16.f32 "
        "{%0,%1,%2,%3}, {%4,%5,%6,%7}, {%8,%9}, {%0,%1,%2,%3};"
        : "+f"(c[0]), "+f"(c[1]), "+f"(c[2]), "+f"(c[3])
        : "r"(a[0]), "r"(a[1]), "r"(a[2]), "r"(a[3]), "r"(b0), "r"(b1));
}
__device__ __forceinline__ uint32_t pack_h2(__half a, __half b) {
    __half2 h = __halves2half2(a, b);
    return *reinterpret_cast<uint32_t*>(&h);
}

// ---------------- fused prep kernel -----------------------------------------
// Range 1: x -> fp16 (float4-vectorized). Range 2: w -> fp16. Range 3: bias.

#define NA4 ((GM * GK) / 4)                 // 4816896
#define NB4 ((GN * GK) / 4)                 // 442368
#define NC4 ((NHEAD * NTOK * NTOK) / 4)     // 57624
#define NTOT4 (NA4 + NB4 + NC4)

__global__ __launch_bounds__(256) void prep_all(
    const float* __restrict__ x, const float* __restrict__ w,
    const float* __restrict__ rel_table, const int* __restrict__ rel_index)
{
    int i = blockIdx.x * 256 + threadIdx.x;
    if (i < NA4) {
        float4 v = *(const float4*)(x + (size_t)i * 4);
        __half2* dst = (__half2*)(g_asp + (size_t)i * 4);
        dst[0] = __floats2half2_rn(v.x, v.y);
        dst[1] = __floats2half2_rn(v.z, v.w);
    } else if (i < NA4 + NB4) {
        int j = i - NA4;
        float4 v = *(const float4*)(w + (size_t)j * 4);
        __half2* dst = (__half2*)(g_bh + (size_t)j * 4);
        dst[0] = __floats2half2_rn(v.x, v.y);
        dst[1] = __floats2half2_rn(v.z, v.w);
    } else if (i < NTOT4) {
        int j = (i - NA4 - NB4) * 4;
#pragma unroll
        for (int e = 0; e < 4; e++) {
            int idx = j + e;
            int h  = idx / (NTOK * NTOK);
            int rj = idx - h * (NTOK * NTOK);
            g_bias[idx] = __ldg(rel_table + __ldg(rel_index + rj) * NHEAD + h);
        }
    }
}

// ---------------- QKV GEMM (mma.sync fp16) ----------------------------------
// BM=128, BN=96, BK=64. 4 warps (2m x 2n), warp tile 64x48.
// 2-stage cp.async, K=768 (12 chunks). Smem rows 128B, (kc ^ row&7) swizzle.

#define NSTAGE 2
#define CHUNKS 12
#define A_BYTES 16384          // 128 rows x 128B
#define B96_BYTES 12288        // 96 rows x 128B
#define STAGE_BYTES (A_BYTES + B96_BYTES)        // 28KB
#define SMEM_TOTAL (NSTAGE * STAGE_BYTES)        // 56KB

__global__ __launch_bounds__(128, 3) void qkv_mma(const float* __restrict__ bias)
{
    extern __shared__ __align__(128) char smem[];
    const uint32_t sb = smem_u32(smem);

    const int tid  = threadIdx.x;
    const int lane = tid & 31;
    const int wid  = tid >> 5;
    const int wm   = wid & 1;        // 0..1 -> 64 rows
    const int wn   = wid >> 1;       // 0..1 -> 48 cols

    const int m0 = blockIdx.y * 128;
    const int h0 = blockIdx.x;       // head index; cols = h0*96 .. h0*96+95

    const __half* agbase = g_asp + (size_t)m0 * GK;
    const __half* bgbase = g_bh + (size_t)(h0 * 96) * GK;

    const int sub  = lane >> 3;
    const int lr   = (lane & 7) + ((sub & 1) << 3);
    const int subh = sub >> 1;

    uint32_t a_rowoff[4];
    int      a_rx[4];
#pragma unroll
    for (int i = 0; i < 4; i++) {
        int row = wm * 64 + i * 16 + lr;
        a_rowoff[i] = (uint32_t)row * 128;
        a_rx[i]     = row & 7;
    }
    uint32_t b_rowoff[3];
    int      b_rx[3];
#pragma unroll
    for (int g = 0; g < 3; g++) {
        int row = wn * 48 + g * 16 + lr;
        b_rowoff[g] = (uint32_t)row * 128;
        b_rx[g]     = row & 7;
    }

    float acc[4][6][4];
#pragma unroll
    for (int i = 0; i < 4; i++)
#pragma unroll
        for (int j = 0; j < 6; j++)
#pragma unroll
            for (int q = 0; q < 4; q++) acc[i][j][q] = 0.0f;

    // prologue: stage chunk 0
    {
        uint32_t aB = sb;
        uint32_t bB = sb + A_BYTES;
#pragma unroll
        for (int l = 0; l < 8; l++) {       // A: 1024 16B-chunks, 8/thread
            int ci = tid + l * 128;
            int r = ci >> 3, kc = ci & 7;
            CP16(aB + r * 128 + ((kc ^ (r & 7)) << 4),
                 agbase + (size_t)r * GK + kc * 8);
        }
#pragma unroll
        for (int l = 0; l < 6; l++) {       // B: 768 16B-chunks, 6/thread
            int ci = tid + l * 128;
            int r = ci >> 3, kc = ci & 7;
            CP16(bB + r * 128 + ((kc ^ (r & 7)) << 4),
                 bgbase + (size_t)r * GK + kc * 8);
        }
        CP_COMMIT();
    }

#pragma unroll 1
    for (int c = 0; c < CHUNKS; c++) {
        if (c + 1 < CHUNKS) {
            int cs = c + 1;
            uint32_t aB = sb + (cs & 1) * STAGE_BYTES;
            uint32_t bB = aB + A_BYTES;
#pragma unroll
            for (int l = 0; l < 8; l++) {
                int ci = tid + l * 128;
                int r = ci >> 3, kc = ci & 7;
                CP16(aB + r * 128 + ((kc ^ (r & 7)) << 4),
                     agbase + (size_t)r * GK + cs * 64 + kc * 8);
            }
#pragma unroll
            for (int l = 0; l < 6; l++) {
                int ci = tid + l * 128;
                int r = ci >> 3, kc = ci & 7;
                CP16(bB + r * 128 + ((kc ^ (r & 7)) << 4),
                     bgbase + (size_t)r * GK + cs * 64 + kc * 8);
            }
            CP_COMMIT();
            CP_WAIT(1);
        } else {
            CP_WAIT(0);
        }
        __syncthreads();

        const uint32_t aB = sb + (c & 1) * STAGE_BYTES;
        const uint32_t bB = aB + A_BYTES;

#pragma unroll
        for (int j = 0; j < 4; j++) {
            uint32_t af[4][4];
#pragma unroll
            for (int i = 0; i < 4; i++) {
                uint32_t addr = aB + a_rowoff[i]
                              + (uint32_t)(((j * 2 + subh) ^ a_rx[i]) << 4);
                ldm_x4(af[i][0], af[i][1], af[i][2], af[i][3], addr);
            }
            uint32_t bf[6][2];
#pragma unroll
            for (int g = 0; g < 3; g++) {
                uint32_t r0, r1, r2, r3;
                uint32_t addr = bB + b_rowoff[g]
                              + (uint32_t)(((j * 2 + subh) ^ b_rx[g]) << 4);
                ldm_x4(r0, r1, r2, r3, addr);
                bf[2 * g][0]     = r0; bf[2 * g][1]     = r2;
                bf[2 * g + 1][0] = r1; bf[2 * g + 1][1] = r3;
            }
#pragma unroll
            for (int i = 0; i < 4; i++)
#pragma unroll
                for (int n = 0; n < 6; n++)
                    mma_f16(acc[i][n], af[i], bf[n][0], bf[n][1]);
        }
        __syncthreads();
    }

    // Epilogue: bias, fold SCALE into Q (single fp16), K/V fp16.
    // One head per CTA: local col lc in 0..95, s3 = lc%3, d = lc/3.
    const int rbase = lane >> 2;
    const int cpair = lane & 3;
#pragma unroll
    for (int i = 0; i < 4; i++) {
#pragma unroll
        for (int half = 0; half < 2; half++) {
            int m = m0 + wm * 64 + i * 16 + rbase + half * 8;
            int b = m / NTOK;
            int tok = m - b * NTOK;
            size_t obase = ((size_t)b * NHEAD + h0) * NTOK * HD + (size_t)tok * HD;
#pragma unroll
            for (int n = 0; n < 6; n++) {
#pragma unroll
                for (int e = 0; e < 2; e++) {
                    int lc = wn * 48 + n * 8 + cpair * 2 + e;
                    float v = acc[i][n][half * 2 + e] + __ldg(&bias[h0 * 96 + lc]);
                    int s3 = lc % 3;
                    int d  = lc / 3;
                    size_t dst = obase + d;
                    if (s3 == 0)      g_qh[dst] = __float2half_rn(v * SCALE);
                    else if (s3 == 1) g_kh[dst] = __float2half_rn(v);
                    else              g_vh[dst] = __float2half_rn(v);
                }
            }
        }
    }
}

// ---------------- tensor-core attention -------------------------------------
// CTA = (h, b). 4 warps. Rows/keys padded 98 -> 112. Row stride 80B in smem.

#define RSTR 40   // halfs per row (80 bytes)

__global__ __launch_bounds__(128) void attn_tc(
    const float* __restrict__ mask,
    float* __restrict__ out)
{
    __shared__ __align__(16) __half sQh[112 * RSTR];
    __shared__ __align__(16) __half sKh[112 * RSTR];
    __shared__ __align__(16) __half sVh[112 * RSTR];

    const int h    = blockIdx.x;
    const int b    = blockIdx.y;
    const int tid  = threadIdx.x;
    const int lane = tid & 31;
    const int w    = tid >> 5;
    const int g    = lane >> 2;   // row group
    const int t    = lane & 3;    // col pair

    const size_t gbase = ((size_t)b * NHEAD + h) * NTOK * HD;
    const uint32_t qhB = smem_u32(sQh);
    const uint32_t khB = smem_u32(sKh);
    const uint32_t vhB = smem_u32(sVh);

    // zero pad rows 98..111
    for (int idx = tid; idx < 14 * 4; idx += 128) {
        int row = 98 + (idx >> 2);
        int q   = idx & 3;
        uint4 z = {0, 0, 0, 0};
        *(uint4*)((char*)sQh + row * 80 + q * 16) = z;
        *(uint4*)((char*)sKh + row * 80 + q * 16) = z;
        *(uint4*)((char*)sVh + row * 80 + q * 16) = z;
    }
    // stage Q/K/V
    for (int idx = tid; idx < 98 * 4; idx += 128) {
        int row = idx >> 2;
        int q   = idx & 3;
        size_t src = gbase + row * 32 + q * 8;
        uint32_t doff = row * 80 + q * 16;
        CP16(qhB + doff, g_qh + src);
        CP16(khB + doff, g_kh + src);
        CP16(vhB + doff, g_vh + src);
    }
    CP_COMMIT();
    CP_WAIT(0);
    __syncthreads();

    const float* maskw = mask + (size_t)(b & (NWIN - 1)) * NTOK * NTOK;
    const float* biash = g_bias + (size_t)h * NTOK * NTOK;

#pragma unroll 1
    for (int mi = 0; mi < 2; mi++) {
        int mt = w + mi * 4;
        if (mt > 6) break;
        const int r0 = mt * 16;

        // ---- Q fragments (2 k16 tiles) --------------------------------------
        uint32_t qh[2][4];
        {
            int qrow = r0 + (lane & 7) + (((lane >> 3) & 1) << 3);
            int qcol = ((lane >> 4) << 3);
#pragma unroll
            for (int kt = 0; kt < 2; kt++) {
                uint32_t off = (uint32_t)qrow * 80 + (uint32_t)(kt * 16 + qcol) * 2;
                ldm_x4(qh[kt][0], qh[kt][1], qh[kt][2], qh[kt][3], qhB + off);
            }
        }

        // ---- S = Q K^T ------------------------------------------------------
        float sc[14][4];
#pragma unroll
        for (int i = 0; i < 14; i++)
#pragma unroll
            for (int q = 0; q < 4; q++) sc[i][q] = 0.0f;

        {
            int krow = (lane & 7) + ((lane >> 4) << 3);
            int kcol = ((lane >> 3) & 1) << 3;
#pragma unroll
            for (int nt2 = 0; nt2 < 7; nt2++) {
                int j0 = nt2 * 16;
                uint32_t k0[4], k1[4];
                uint32_t roff = (uint32_t)(j0 + krow) * 80;
                ldm_x4(k0[0], k0[1], k0[2], k0[3], khB + roff + (uint32_t)(kcol) * 2);
                ldm_x4(k1[0], k1[1], k1[2], k1[3], khB + roff + (uint32_t)(16 + kcol) * 2);
                float* aA = sc[2 * nt2];
                float* aB = sc[2 * nt2 + 1];
                mma_f16(aA, qh[0], k0[0], k0[1]);
                mma_f16(aA, qh[1], k1[0], k1[1]);
                mma_f16(aB, qh[0], k0[2], k0[3]);
                mma_f16(aB, qh[1], k1[2], k1[3]);
            }
        }

        // ---- bias + mask + softmax (registers only) -------------------------
#pragma unroll
        for (int h2 = 0; h2 < 2; h2++) {
            int row = r0 + g + h2 * 8;
            float mx = -1e30f;
            bool rok = (row < NTOK);
#pragma unroll
            for (int i = 0; i < 14; i++) {
                int jc = 8 * i + 2 * t;
                float s0, s1;
                if (rok && jc < NTOK) {
                    float2 mk = *(const float2*)(maskw + row * NTOK + jc);
                    float2 bi = *(const float2*)(biash + row * NTOK + jc);
                    s0 = sc[i][h2 * 2]     + mk.x + bi.x;
                    s1 = sc[i][h2 * 2 + 1] + mk.y + bi.y;
                } else {
                    s0 = -1e30f; s1 = -1e30f;
                }
                sc[i][h2 * 2]     = s0;
                sc[i][h2 * 2 + 1] = s1;
                mx = fmaxf(mx, fmaxf(s0, s1));
            }
            mx = fmaxf(mx, __shfl_xor_sync(0xffffffffu, mx, 1));
            mx = fmaxf(mx, __shfl_xor_sync(0xffffffffu, mx, 2));
            float sum = 0.0f;
#pragma unroll
            for (int i = 0; i < 14; i++) {
                float p0 = __expf(sc[i][h2 * 2]     - mx);
                float p1 = __expf(sc[i][h2 * 2 + 1] - mx);
                sc[i][h2 * 2]     = p0;
                sc[i][h2 * 2 + 1] = p1;
                sum += p0 + p1;
            }
            sum += __shfl_xor_sync(0xffffffffu, sum, 1);
            sum += __shfl_xor_sync(0xffffffffu, sum, 2);
            float inv = 1.0f / sum;
#pragma unroll
            for (int i = 0; i < 14; i++) {
                sc[i][h2 * 2]     *= inv;
                sc[i][h2 * 2 + 1] *= inv;
            }
        }

        // ---- O = P V (P split hi/lo for accuracy) ---------------------------
        float o[4][4];
#pragma unroll
        for (int n = 0; n < 4; n++)
#pragma unroll
            for (int q = 0; q < 4; q++) o[n][q] = 0.0f;

        {
            int vrow = (lane & 7) + (((lane >> 3) & 1) << 3);
            int vcol = (lane >> 4) << 3;
#pragma unroll
            for (int kk = 0; kk < 7; kk++) {
                uint32_t ph[4], pl[4];
                {
                    float e0 = sc[2 * kk][0],     e1 = sc[2 * kk][1];
                    float e2 = sc[2 * kk][2],     e3 = sc[2 * kk][3];
                    float e4 = sc[2 * kk + 1][0], e5 = sc[2 * kk + 1][1];
                    float e6 = sc[2 * kk + 1][2], e7 = sc[2 * kk + 1][3];
                    __half h0 = __float2half_rn(e0), h1 = __float2half_rn(e1);
                    __half h2 = __float2half_rn(e2), h3 = __float2half_rn(e3);
                    __half h4 = __float2half_rn(e4), h5 = __float2half_rn(e5);
                    __half h6 = __float2half_rn(e6), h7 = __float2half_rn(e7);
                    ph[0] = pack_h2(h0, h1);
                    ph[1] = pack_h2(h2, h3);
                    ph[2] = pack_h2(h4, h5);
                    ph[3] = pack_h2(h6, h7);
                    pl[0] = pack_h2(__float2half_rn(e0 - __half2float(h0)),
                                    __float2half_rn(e1 - __half2float(h1)));
                    pl[1] = pack_h2(__float2half_rn(e2 - __half2float(h2)),
                                    __float2half_rn(e3 - __half2float(h3)));
                    pl[2] = pack_h2(__float2half_rn(e4 - __half2float(h4)),
                                    __float2half_rn(e5 - __half2float(h5)));
                    pl[3] = pack_h2(__float2half_rn(e6 - __half2float(h6)),
                                    __float2half_rn(e7 - __half2float(h7)));
                }
                int j0 = kk * 16;
                uint32_t v0[4], v16[4];
                uint32_t roff = (uint32_t)(j0 + vrow) * 80;
                ldm_x4_t(v0[0], v0[1], v0[2], v0[3],  vhB + roff + (uint32_t)vcol * 2);
                ldm_x4_t(v16[0], v16[1], v16[2], v16[3],
                         vhB + roff + (uint32_t)(16 + vcol) * 2);
                mma_f16(o[0], ph, v0[0], v0[1]);
                mma_f16(o[1], ph, v0[2], v0[3]);
                mma_f16(o[2], ph, v16[0], v16[1]);
                mma_f16(o[3], ph, v16[2], v16[3]);
                mma_f16(o[0], pl, v0[0], v0[1]);
                mma_f16(o[1], pl, v0[2], v0[3]);
                mma_f16(o[2], pl, v16[0], v16[1]);
                mma_f16(o[3], pl, v16[2], v16[3]);
            }
        }

        // ---- store ----------------------------------------------------------
        {
            int rowA = r0 + g;
            int rowB = rowA + 8;
            if (rowA < NTOK) {
                float* dst = out + ((size_t)b * NTOK + rowA) * DIMC + h * HD;
#pragma unroll
                for (int n = 0; n < 4; n++) {
                    float2 v = {o[n][0], o[n][1]};
                    *(float2*)(dst + n * 8 + 2 * t) = v;
                }
            }
            if (rowB < NTOK) {
                float* dst = out + ((size_t)b * NTOK + rowB) * DIMC + h * HD;
#pragma unroll
                for (int n = 0; n < 4; n++) {
                    float2 v = {o[n][2], o[n][3]};
                    *(float2*)(dst + n * 8 + 2 * t) = v;
                }
            }
        }
    }
}

// ------------------------- launch ------------------------------------------

extern "C" void kernel_launch(void* const* d_in, const int* in_sizes, int n_in,
                              void* d_out, int out_size)
{
    const float* x         = (const float*)d_in[0];
    const float* mask      = (const float*)d_in[1];
    const float* qkv_w     = (const float*)d_in[2];
    const float* qkv_b     = (const float*)d_in[3];
    const float* rel_table = (const float*)d_in[4];
    const int*   rel_index = (const int*)  d_in[5];
    float* out = (float*)d_out;

    prep_all<<<(NTOT4 + 255) / 256, 256>>>(x, qkv_w, rel_table, rel_index);

    cudaFuncSetAttribute(qkv_mma, cudaFuncAttributeMaxDynamicSharedMemorySize,
                         SMEM_TOTAL);
    dim3 g1(NHEAD, GM / 128);       // (24, 196) — one head per CTA in x
    qkv_mma<<<g1, 128, SMEM_TOTAL>>>(qkv_b);

    dim3 g2(NHEAD, B_);             // (24, 256)
    attn_tc<<<g2, 128>>>(mask, out);
}

// round 9
// speedup vs baseline: 1.7506x; 1.2663x over previous
#include <cuda_runtime.h>
#include <cuda_fp16.h>
#include <math.h>
#include <stdint.h>

// ---------------------------------------------------------------------------
// WindowAttention (Swin): B_=256, N=98, DIM=768, NH=24, HD=32, NW=64
// Phase 1: QKV GEMM, mma.sync fp16. CTA 128x96 (one head), 4 warps (64x48),
//          2-stage cp.async, 3 CTAs/SM, smem-staged coalesced epilogue.
// Phase 2: tensor-core attention (single-fp16 P), fused bias table
// ---------------------------------------------------------------------------

#define B_    256
#define NTOK  98
#define DIMC  768
#define NHEAD 24
#define HD    32
#define NWIN  64
#define SCALE 0.17677669529663687f

#define GM (B_ * NTOK)     // 25088
#define GK DIMC            // 768
#define GN (3 * DIMC)      // 2304

// Scratch
__device__ __half g_asp[(size_t)GM * GK];      // x fp16
__device__ __half g_bh[(size_t)GN * GK];       // w fp16
__device__ __half g_qh[B_ * NHEAD * NTOK * HD];
__device__ __half g_kh[B_ * NHEAD * NTOK * HD];
__device__ __half g_vh[B_ * NHEAD * NTOK * HD];
__device__ float  g_bias[NHEAD * NTOK * NTOK]; // fused rel-pos bias [h][r][j]

// ---------------- helpers ---------------------------------------------------

__device__ __forceinline__ uint32_t smem_u32(const void* p) {
    uint32_t a;
    asm("{ .reg .u64 t; cvta.to.shared.u64 t, %1; cvt.u32.u64 %0, t; }" : "=r"(a) : "l"(p));
    return a;
}
#define CP16(dst, src) \
    asm volatile("cp.async.cg.shared.global [%0], [%1], 16;" :: "r"(dst), "l"(src) : "memory")
#define CP_COMMIT() asm volatile("cp.async.commit_group;" ::: "memory")
#define CP_WAIT(n)  asm volatile("cp.async.wait_group %0;" :: "n"(n) : "memory")

__device__ __forceinline__ void ldm_x4(uint32_t& r0, uint32_t& r1, uint32_t& r2,
                                       uint32_t& r3, uint32_t addr) {
    asm volatile("ldmatrix.sync.aligned.m8n8.x4.shared.b16 {%0,%1,%2,%3}, [%4];"
                 : "=r"(r0), "=r"(r1), "=r"(r2), "=r"(r3) : "r"(addr));
}
__device__ __forceinline__ void ldm_x4_t(uint32_t& r0, uint32_t& r1, uint32_t& r2,
                                         uint32_t& r3, uint32_t addr) {
    asm volatile("ldmatrix.sync.aligned.m8n8.x4.trans.shared.b16 {%0,%1,%2,%3}, [%4];"
                 : "=r"(r0), "=r"(r1), "=r"(r2), "=r"(r3) : "r"(addr));
}
__device__ __forceinline__ void mma_f16(float* c, const uint32_t* a, uint32_t b0, uint32_t b1) {
    asm volatile(
        "mma.sync.aligned.m16n8k16.row.col.f32.f16.f16.f32 "
        "{%0,%1,%2,%3}, {%4,%5,%6,%7}, {%8,%9}, {%0,%1,%2,%3};"
        : "+f"(c[0]), "+f"(c[1]), "+f"(c[2]), "+f"(c[3])
        : "r"(a[0]), "r"(a[1]), "r"(a[2]), "r"(a[3]), "r"(b0), "r"(b1));
}

// ---------------- fused prep kernel -----------------------------------------

#define NA4 ((GM * GK) / 4)
#define NB4 ((GN * GK) / 4)
#define NC4 ((NHEAD * NTOK * NTOK) / 4)
#define NTOT4 (NA4 + NB4 + NC4)

__global__ __launch_bounds__(256) void prep_all(
    const float* __restrict__ x, const float* __restrict__ w,
    const float* __restrict__ rel_table, const int* __restrict__ rel_index)
{
    int i = blockIdx.x * 256 + threadIdx.x;
    if (i < NA4) {
        float4 v = *(const float4*)(x + (size_t)i * 4);
        __half2* dst = (__half2*)(g_asp + (size_t)i * 4);
        dst[0] = __floats2half2_rn(v.x, v.y);
        dst[1] = __floats2half2_rn(v.z, v.w);
    } else if (i < NA4 + NB4) {
        int j = i - NA4;
        float4 v = *(const float4*)(w + (size_t)j * 4);
        __half2* dst = (__half2*)(g_bh + (size_t)j * 4);
        dst[0] = __floats2half2_rn(v.x, v.y);
        dst[1] = __floats2half2_rn(v.z, v.w);
    } else if (i < NTOT4) {
        int j = (i - NA4 - NB4) * 4;
#pragma unroll
        for (int e = 0; e < 4; e++) {
            int idx = j + e;
            int h  = idx / (NTOK * NTOK);
            int rj = idx - h * (NTOK * NTOK);
            g_bias[idx] = __ldg(rel_table + __ldg(rel_index + rj) * NHEAD + h);
        }
    }
}

// ---------------- QKV GEMM (mma.sync fp16) ----------------------------------
// BM=128, BN=96, BK=64. 4 warps (2m x 2n), warp tile 64x48.
// 2-stage cp.async, K=768 (12 chunks). Smem rows 128B, (kc ^ row&7) swizzle.

#define NSTAGE 2
#define CHUNKS 12
#define A_BYTES 16384
#define B96_BYTES 12288
#define STAGE_BYTES (A_BYTES + B96_BYTES)        // 28KB
#define SMEM_TOTAL (NSTAGE * STAGE_BYTES)        // 56KB
#define EP_PAD 104                               // epilogue smem row stride (halfs)

__global__ __launch_bounds__(128, 3) void qkv_mma(const float* __restrict__ bias)
{
    extern __shared__ __align__(128) char smem[];
    const uint32_t sb = smem_u32(smem);

    const int tid  = threadIdx.x;
    const int lane = tid & 31;
    const int wid  = tid >> 5;
    const int wm   = wid & 1;
    const int wn   = wid >> 1;

    const int m0 = blockIdx.y * 128;
    const int h0 = blockIdx.x;

    const __half* agbase = g_asp + (size_t)m0 * GK;
    const __half* bgbase = g_bh + (size_t)(h0 * 96) * GK;

    const int sub  = lane >> 3;
    const int lr   = (lane & 7) + ((sub & 1) << 3);
    const int subh = sub >> 1;

    uint32_t a_rowoff[4];
    int      a_rx[4];
#pragma unroll
    for (int i = 0; i < 4; i++) {
        int row = wm * 64 + i * 16 + lr;
        a_rowoff[i] = (uint32_t)row * 128;
        a_rx[i]     = row & 7;
    }
    uint32_t b_rowoff[3];
    int      b_rx[3];
#pragma unroll
    for (int g = 0; g < 3; g++) {
        int row = wn * 48 + g * 16 + lr;
        b_rowoff[g] = (uint32_t)row * 128;
        b_rx[g]     = row & 7;
    }

    float acc[4][6][4];
#pragma unroll
    for (int i = 0; i < 4; i++)
#pragma unroll
        for (int j = 0; j < 6; j++)
#pragma unroll
            for (int q = 0; q < 4; q++) acc[i][j][q] = 0.0f;

    // prologue: stage chunk 0
    {
        uint32_t aB = sb;
        uint32_t bB = sb + A_BYTES;
#pragma unroll
        for (int l = 0; l < 8; l++) {
            int ci = tid + l * 128;
            int r = ci >> 3, kc = ci & 7;
            CP16(aB + r * 128 + ((kc ^ (r & 7)) << 4),
                 agbase + (size_t)r * GK + kc * 8);
        }
#pragma unroll
        for (int l = 0; l < 6; l++) {
            int ci = tid + l * 128;
            int r = ci >> 3, kc = ci & 7;
            CP16(bB + r * 128 + ((kc ^ (r & 7)) << 4),
                 bgbase + (size_t)r * GK + kc * 8);
        }
        CP_COMMIT();
    }

#pragma unroll 1
    for (int c = 0; c < CHUNKS; c++) {
        if (c + 1 < CHUNKS) {
            int cs = c + 1;
            uint32_t aB = sb + (cs & 1) * STAGE_BYTES;
            uint32_t bB = aB + A_BYTES;
#pragma unroll
            for (int l = 0; l < 8; l++) {
                int ci = tid + l * 128;
                int r = ci >> 3, kc = ci & 7;
                CP16(aB + r * 128 + ((kc ^ (r & 7)) << 4),
                     agbase + (size_t)r * GK + cs * 64 + kc * 8);
            }
#pragma unroll
            for (int l = 0; l < 6; l++) {
                int ci = tid + l * 128;
                int r = ci >> 3, kc = ci & 7;
                CP16(bB + r * 128 + ((kc ^ (r & 7)) << 4),
                     bgbase + (size_t)r * GK + cs * 64 + kc * 8);
            }
            CP_COMMIT();
            CP_WAIT(1);
        } else {
            CP_WAIT(0);
        }
        __syncthreads();

        const uint32_t aB = sb + (c & 1) * STAGE_BYTES;
        const uint32_t bB = aB + A_BYTES;

#pragma unroll
        for (int j = 0; j < 4; j++) {
            uint32_t af[4][4];
#pragma unroll
            for (int i = 0; i < 4; i++) {
                uint32_t addr = aB + a_rowoff[i]
                              + (uint32_t)(((j * 2 + subh) ^ a_rx[i]) << 4);
                ldm_x4(af[i][0], af[i][1], af[i][2], af[i][3], addr);
            }
            uint32_t bf[6][2];
#pragma unroll
            for (int g = 0; g < 3; g++) {
                uint32_t r0, r1, r2, r3;
                uint32_t addr = bB + b_rowoff[g]
                              + (uint32_t)(((j * 2 + subh) ^ b_rx[g]) << 4);
                ldm_x4(r0, r1, r2, r3, addr);
                bf[2 * g][0]     = r0; bf[2 * g][1]     = r2;
                bf[2 * g + 1][0] = r1; bf[2 * g + 1][1] = r3;
            }
#pragma unroll
            for (int i = 0; i < 4; i++)
#pragma unroll
                for (int n = 0; n < 6; n++)
                    mma_f16(acc[i][n], af[i], bf[n][0], bf[n][1]);
        }
        __syncthreads();
    }

    // ---- epilogue phase 1: acc -> smem tile (bias + scale applied) ----------
    __half* ep = (__half*)smem;
    const int rbase = lane >> 2;
    const int cpair = lane & 3;
#pragma unroll
    for (int i = 0; i < 4; i++) {
#pragma unroll
        for (int half = 0; half < 2; half++) {
            int row = wm * 64 + i * 16 + rbase + half * 8;
#pragma unroll
            for (int n = 0; n < 6; n++) {
                int lc0 = wn * 48 + n * 8 + cpair * 2;
                float v0 = acc[i][n][half * 2]     + __ldg(&bias[h0 * 96 + lc0]);
                float v1 = acc[i][n][half * 2 + 1] + __ldg(&bias[h0 * 96 + lc0 + 1]);
                if (lc0 % 3 == 0)       v0 *= SCALE;
                if ((lc0 + 1) % 3 == 0) v1 *= SCALE;
                *(__half2*)&ep[row * EP_PAD + lc0] = __floats2half2_rn(v0, v1);
            }
        }
    }
    __syncthreads();

    // ---- epilogue phase 2: smem -> global, coalesced -------------------------
    // 1536 16B-chunks: 128 rows x 3 streams x 4 chunks; 4 lanes cover one
    // (row,stream) contiguously -> warp stores 512B contiguous per stream.
#pragma unroll
    for (int l = 0; l < 12; l++) {
        int ci    = tid + l * 128;
        int chunk = ci & 3;
        int rs    = ci >> 2;
        int row   = rs & 127;
        int s     = rs >> 7;
        int m   = m0 + row;
        int b   = m / NTOK;
        int tok = m - b * NTOK;
        size_t dst = ((size_t)b * NHEAD + h0) * NTOK * HD + (size_t)tok * HD
                   + chunk * 8;
        __half tmp[8];
#pragma unroll
        for (int d8 = 0; d8 < 8; d8++)
            tmp[d8] = ep[row * EP_PAD + s + 3 * (chunk * 8 + d8)];
        __half* base = (s == 0) ? g_qh : (s == 1) ? g_kh : g_vh;
        *(uint4*)(base + dst) = *(uint4*)tmp;
    }
}

// ---------------- tensor-core attention -------------------------------------
// CTA = (h, b). 4 warps. Rows/keys padded 98 -> 112. Row stride 80B in smem.

#define RSTR 40   // halfs per row (80 bytes)

__global__ __launch_bounds__(128) void attn_tc(
    const float* __restrict__ mask,
    float* __restrict__ out)
{
    __shared__ __align__(16) __half sQh[112 * RSTR];
    __shared__ __align__(16) __half sKh[112 * RSTR];
    __shared__ __align__(16) __half sVh[112 * RSTR];

    const int h    = blockIdx.x;
    const int b    = blockIdx.y;
    const int tid  = threadIdx.x;
    const int lane = tid & 31;
    const int w    = tid >> 5;
    const int g    = lane >> 2;
    const int t    = lane & 3;

    const size_t gbase = ((size_t)b * NHEAD + h) * NTOK * HD;
    const uint32_t qhB = smem_u32(sQh);
    const uint32_t khB = smem_u32(sKh);
    const uint32_t vhB = smem_u32(sVh);

    for (int idx = tid; idx < 14 * 4; idx += 128) {
        int row = 98 + (idx >> 2);
        int q   = idx & 3;
        uint4 z = {0, 0, 0, 0};
        *(uint4*)((char*)sQh + row * 80 + q * 16) = z;
        *(uint4*)((char*)sKh + row * 80 + q * 16) = z;
        *(uint4*)((char*)sVh + row * 80 + q * 16) = z;
    }
    for (int idx = tid; idx < 98 * 4; idx += 128) {
        int row = idx >> 2;
        int q   = idx & 3;
        size_t src = gbase + row * 32 + q * 8;
        uint32_t doff = row * 80 + q * 16;
        CP16(qhB + doff, g_qh + src);
        CP16(khB + doff, g_kh + src);
        CP16(vhB + doff, g_vh + src);
    }
    CP_COMMIT();
    CP_WAIT(0);
    __syncthreads();

    const float* maskw = mask + (size_t)(b & (NWIN - 1)) * NTOK * NTOK;
    const float* biash = g_bias + (size_t)h * NTOK * NTOK;

#pragma unroll 1
    for (int mi = 0; mi < 2; mi++) {
        int mt = w + mi * 4;
        if (mt > 6) break;
        const int r0 = mt * 16;

        uint32_t qh[2][4];
        {
            int qrow = r0 + (lane & 7) + (((lane >> 3) & 1) << 3);
            int qcol = ((lane >> 4) << 3);
#pragma unroll
            for (int kt = 0; kt < 2; kt++) {
                uint32_t off = (uint32_t)qrow * 80 + (uint32_t)(kt * 16 + qcol) * 2;
                ldm_x4(qh[kt][0], qh[kt][1], qh[kt][2], qh[kt][3], qhB + off);
            }
        }

        float sc[14][4];
#pragma unroll
        for (int i = 0; i < 14; i++)
#pragma unroll
            for (int q = 0; q < 4; q++) sc[i][q] = 0.0f;

        {
            int krow = (lane & 7) + ((lane >> 4) << 3);
            int kcol = ((lane >> 3) & 1) << 3;
#pragma unroll
            for (int nt2 = 0; nt2 < 7; nt2++) {
                int j0 = nt2 * 16;
                uint32_t k0[4], k1[4];
                uint32_t roff = (uint32_t)(j0 + krow) * 80;
                ldm_x4(k0[0], k0[1], k0[2], k0[3], khB + roff + (uint32_t)(kcol) * 2);
                ldm_x4(k1[0], k1[1], k1[2], k1[3], khB + roff + (uint32_t)(16 + kcol) * 2);
                float* aA = sc[2 * nt2];
                float* aB = sc[2 * nt2 + 1];
                mma_f16(aA, qh[0], k0[0], k0[1]);
                mma_f16(aA, qh[1], k1[0], k1[1]);
                mma_f16(aB, qh[0], k0[2], k0[3]);
                mma_f16(aB, qh[1], k1[2], k1[3]);
            }
        }

#pragma unroll
        for (int h2 = 0; h2 < 2; h2++) {
            int row = r0 + g + h2 * 8;
            float mx = -1e30f;
            bool rok = (row < NTOK);
#pragma unroll
            for (int i = 0; i < 14; i++) {
                int jc = 8 * i + 2 * t;
                float s0, s1;
                if (rok && jc < NTOK) {
                    float2 mk = *(const float2*)(maskw + row * NTOK + jc);
                    float2 bi = *(const float2*)(biash + row * NTOK + jc);
                    s0 = sc[i][h2 * 2]     + mk.x + bi.x;
                    s1 = sc[i][h2 * 2 + 1] + mk.y + bi.y;
                } else {
                    s0 = -1e30f; s1 = -1e30f;
                }
                sc[i][h2 * 2]     = s0;
                sc[i][h2 * 2 + 1] = s1;
                mx = fmaxf(mx, fmaxf(s0, s1));
            }
            mx = fmaxf(mx, __shfl_xor_sync(0xffffffffu, mx, 1));
            mx = fmaxf(mx, __shfl_xor_sync(0xffffffffu, mx, 2));
            float sum = 0.0f;
#pragma unroll
            for (int i = 0; i < 14; i++) {
                float p0 = __expf(sc[i][h2 * 2]     - mx);
                float p1 = __expf(sc[i][h2 * 2 + 1] - mx);
                sc[i][h2 * 2]     = p0;
                sc[i][h2 * 2 + 1] = p1;
                sum += p0 + p1;
            }
            sum += __shfl_xor_sync(0xffffffffu, sum, 1);
            sum += __shfl_xor_sync(0xffffffffu, sum, 2);
            float inv = 1.0f / sum;
#pragma unroll
            for (int i = 0; i < 14; i++) {
                sc[i][h2 * 2]     *= inv;
                sc[i][h2 * 2 + 1] *= inv;
            }
        }

        // ---- O = P V (single-fp16 P) ----------------------------------------
        float o[4][4];
#pragma unroll
        for (int n = 0; n < 4; n++)
#pragma unroll
            for (int q = 0; q < 4; q++) o[n][q] = 0.0f;

        {
            int vrow = (lane & 7) + (((lane >> 3) & 1) << 3);
            int vcol = (lane >> 4) << 3;
#pragma unroll
            for (int kk = 0; kk < 7; kk++) {
                uint32_t ph[4];
                {
                    __half2 p0 = __floats2half2_rn(sc[2 * kk][0],     sc[2 * kk][1]);
                    __half2 p1 = __floats2half2_rn(sc[2 * kk][2],     sc[2 * kk][3]);
                    __half2 p2 = __floats2half2_rn(sc[2 * kk + 1][0], sc[2 * kk + 1][1]);
                    __half2 p3 = __floats2half2_rn(sc[2 * kk + 1][2], sc[2 * kk + 1][3]);
                    ph[0] = *(uint32_t*)&p0;
                    ph[1] = *(uint32_t*)&p1;
                    ph[2] = *(uint32_t*)&p2;
                    ph[3] = *(uint32_t*)&p3;
                }
                int j0 = kk * 16;
                uint32_t v0[4], v16[4];
                uint32_t roff = (uint32_t)(j0 + vrow) * 80;
                ldm_x4_t(v0[0], v0[1], v0[2], v0[3],  vhB + roff + (uint32_t)vcol * 2);
                ldm_x4_t(v16[0], v16[1], v16[2], v16[3],
                         vhB + roff + (uint32_t)(16 + vcol) * 2);
                mma_f16(o[0], ph, v0[0], v0[1]);
                mma_f16(o[1], ph, v0[2], v0[3]);
                mma_f16(o[2], ph, v16[0], v16[1]);
                mma_f16(o[3], ph, v16[2], v16[3]);
            }
        }

        {
            int rowA = r0 + g;
            int rowB = rowA + 8;
            if (rowA < NTOK) {
                float* dst = out + ((size_t)b * NTOK + rowA) * DIMC + h * HD;
#pragma unroll
                for (int n = 0; n < 4; n++) {
                    float2 v = {o[n][0], o[n][1]};
                    *(float2*)(dst + n * 8 + 2 * t) = v;
                }
            }
            if (rowB < NTOK) {
                float* dst = out + ((size_t)b * NTOK + rowB) * DIMC + h * HD;
#pragma unroll
                for (int n = 0; n < 4; n++) {
                    float2 v = {o[n][2], o[n][3]};
                    *(float2*)(dst + n * 8 + 2 * t) = v;
                }
            }
        }
    }
}

// ------------------------- launch ------------------------------------------

extern "C" void kernel_launch(void* const* d_in, const int* in_sizes, int n_in,
                              void* d_out, int out_size)
{
    const float* x         = (const float*)d_in[0];
    const float* mask      = (const float*)d_in[1];
    const float* qkv_w     = (const float*)d_in[2];
    const float* qkv_b     = (const float*)d_in[3];
    const float* rel_table = (const float*)d_in[4];
    const int*   rel_index = (const int*)  d_in[5];
    float* out = (float*)d_out;

    prep_all<<<(NTOT4 + 255) / 256, 256>>>(x, qkv_w, rel_table, rel_index);

    cudaFuncSetAttribute(qkv_mma, cudaFuncAttributeMaxDynamicSharedMemorySize,
                         SMEM_TOTAL);
    dim3 g1(NHEAD, GM / 128);       // (24, 196)
    qkv_mma<<<g1, 128, SMEM_TOTAL>>>(qkv_b);

    dim3 g2(NHEAD, B_);             // (24, 256)
    attn_tc<<<g2, 128>>>(mask, out);
}

// round 10
// speedup vs baseline: 1.7810x; 1.0173x over previous
#include <cuda_runtime.h>
#include <cuda_fp16.h>
#include <math.h>
#include <stdint.h>

// ---------------------------------------------------------------------------
// WindowAttention (Swin): B_=256, N=98, DIM=768, NH=24, HD=32, NW=64
// Phase 1: QKV GEMM, mma.sync fp16. CTA 128x96 (one head), 4 warps (64x48),
//          2-stage cp.async, 3 CTAs/SM, smem-staged coalesced epilogue.
// Phase 2: tensor-core attention, 2 windows per CTA with cp.async prefetch,
//          fused mask+bias table.
// ---------------------------------------------------------------------------

#define B_    256
#define NTOK  98
#define DIMC  768
#define NHEAD 24
#define HD    32
#define NWIN  64
#define SCALE 0.17677669529663687f

#define GM (B_ * NTOK)     // 25088
#define GK DIMC            // 768
#define GN (3 * DIMC)      // 2304
#define NN (NTOK * NTOK)   // 9604

// Scratch
__device__ __half g_asp[(size_t)GM * GK];      // x fp16
__device__ __half g_bh[(size_t)GN * GK];       // w fp16
__device__ __half g_qh[B_ * NHEAD * NTOK * HD];
__device__ __half g_kh[B_ * NHEAD * NTOK * HD];
__device__ __half g_vh[B_ * NHEAD * NTOK * HD];
__device__ float  g_cmb[NWIN * NHEAD * NN];    // mask + rel-pos bias [w][h][r][j]

// ---------------- helpers ---------------------------------------------------

__device__ __forceinline__ uint32_t smem_u32(const void* p) {
    uint32_t a;
    asm("{ .reg .u64 t; cvta.to.shared.u64 t, %1; cvt.u32.u64 %0, t; }" : "=r"(a) : "l"(p));
    return a;
}
#define CP16(dst, src) \
    asm volatile("cp.async.cg.shared.global [%0], [%1], 16;" :: "r"(dst), "l"(src) : "memory")
#define CP_COMMIT() asm volatile("cp.async.commit_group;" ::: "memory")
#define CP_WAIT(n)  asm volatile("cp.async.wait_group %0;" :: "n"(n) : "memory")

__device__ __forceinline__ void ldm_x4(uint32_t& r0, uint32_t& r1, uint32_t& r2,
                                       uint32_t& r3, uint32_t addr) {
    asm volatile("ldmatrix.sync.aligned.m8n8.x4.shared.b16 {%0,%1,%2,%3}, [%4];"
                 : "=r"(r0), "=r"(r1), "=r"(r2), "=r"(r3) : "r"(addr));
}
__device__ __forceinline__ void ldm_x4_t(uint32_t& r0, uint32_t& r1, uint32_t& r2,
                                         uint32_t& r3, uint32_t addr) {
    asm volatile("ldmatrix.sync.aligned.m8n8.x4.trans.shared.b16 {%0,%1,%2,%3}, [%4];"
                 : "=r"(r0), "=r"(r1), "=r"(r2), "=r"(r3) : "r"(addr));
}
__device__ __forceinline__ void mma_f16(float* c, const uint32_t* a, uint32_t b0, uint32_t b1) {
    asm volatile(
        "mma.sync.aligned.m16n8k16.row.col.f32.f16.f16.f32 "
        "{%0,%1,%2,%3}, {%4,%5,%6,%7}, {%8,%9}, {%0,%1,%2,%3};"
        : "+f"(c[0]), "+f"(c[1]), "+f"(c[2]), "+f"(c[3])
        : "r"(a[0]), "r"(a[1]), "r"(a[2]), "r"(a[3]), "r"(b0), "r"(b1));
}

// ---------------- fused prep kernel -----------------------------------------
// Range 1: x -> fp16. Range 2: w -> fp16. Range 3: cmb = mask + bias gather.

#define NA4 ((GM * GK) / 4)
#define NB4 ((GN * GK) / 4)
#define NC4 ((NWIN * NHEAD * NN) / 4)
#define NTOT4 (NA4 + NB4 + NC4)

__global__ __launch_bounds__(256) void prep_all(
    const float* __restrict__ x, const float* __restrict__ w,
    const float* __restrict__ mask,
    const float* __restrict__ rel_table, const int* __restrict__ rel_index)
{
    int i = blockIdx.x * 256 + threadIdx.x;
    if (i < NA4) {
        float4 v = *(const float4*)(x + (size_t)i * 4);
        __half2* dst = (__half2*)(g_asp + (size_t)i * 4);
        dst[0] = __floats2half2_rn(v.x, v.y);
        dst[1] = __floats2half2_rn(v.z, v.w);
    } else if (i < NA4 + NB4) {
        int j = i - NA4;
        float4 v = *(const float4*)(w + (size_t)j * 4);
        __half2* dst = (__half2*)(g_bh + (size_t)j * 4);
        dst[0] = __floats2half2_rn(v.x, v.y);
        dst[1] = __floats2half2_rn(v.z, v.w);
    } else if (i < NTOT4) {
        // quad never crosses a (w,h) boundary: NN % 4 == 0
        size_t q  = (size_t)(i - NA4 - NB4) * 4;
        int wh = (int)(q / NN);
        int rj = (int)(q - (size_t)wh * NN);
        int wi = wh / NHEAD;
        int h  = wh - wi * NHEAD;
        float4 mk = *(const float4*)(mask + (size_t)wi * NN + rj);
        int4   id = *(const int4*)(rel_index + rj);
        float4 o;
        o.x = mk.x + __ldg(rel_table + id.x * NHEAD + h);
        o.y = mk.y + __ldg(rel_table + id.y * NHEAD + h);
        o.z = mk.z + __ldg(rel_table + id.z * NHEAD + h);
        o.w = mk.w + __ldg(rel_table + id.w * NHEAD + h);
        *(float4*)(g_cmb + q) = o;
    }
}

// ---------------- QKV GEMM (mma.sync fp16) ----------------------------------
// BM=128, BN=96, BK=64. 4 warps (2m x 2n), warp tile 64x48.
// 2-stage cp.async, K=768 (12 chunks). Smem rows 128B, (kc ^ row&7) swizzle.

#define NSTAGE 2
#define CHUNKS 12
#define A_BYTES 16384
#define B96_BYTES 12288
#define STAGE_BYTES (A_BYTES + B96_BYTES)        // 28KB
#define SMEM_TOTAL (NSTAGE * STAGE_BYTES)        // 56KB
#define EP_PAD 104

__global__ __launch_bounds__(128, 3) void qkv_mma(const float* __restrict__ bias)
{
    extern __shared__ __align__(128) char smem[];
    const uint32_t sb = smem_u32(smem);

    const int tid  = threadIdx.x;
    const int lane = tid & 31;
    const int wid  = tid >> 5;
    const int wm   = wid & 1;
    const int wn   = wid >> 1;

    const int m0 = blockIdx.y * 128;
    const int h0 = blockIdx.x;

    const __half* agbase = g_asp + (size_t)m0 * GK;
    const __half* bgbase = g_bh + (size_t)(h0 * 96) * GK;

    const int sub  = lane >> 3;
    const int lr   = (lane & 7) + ((sub & 1) << 3);
    const int subh = sub >> 1;

    uint32_t a_rowoff[4];
    int      a_rx[4];
#pragma unroll
    for (int i = 0; i < 4; i++) {
        int row = wm * 64 + i * 16 + lr;
        a_rowoff[i] = (uint32_t)row * 128;
        a_rx[i]     = row & 7;
    }
    uint32_t b_rowoff[3];
    int      b_rx[3];
#pragma unroll
    for (int g = 0; g < 3; g++) {
        int row = wn * 48 + g * 16 + lr;
        b_rowoff[g] = (uint32_t)row * 128;
        b_rx[g]     = row & 7;
    }

    float acc[4][6][4];
#pragma unroll
    for (int i = 0; i < 4; i++)
#pragma unroll
        for (int j = 0; j < 6; j++)
#pragma unroll
            for (int q = 0; q < 4; q++) acc[i][j][q] = 0.0f;

    {
        uint32_t aB = sb;
        uint32_t bB = sb + A_BYTES;
#pragma unroll
        for (int l = 0; l < 8; l++) {
            int ci = tid + l * 128;
            int r = ci >> 3, kc = ci & 7;
            CP16(aB + r * 128 + ((kc ^ (r & 7)) << 4),
                 agbase + (size_t)r * GK + kc * 8);
        }
#pragma unroll
        for (int l = 0; l < 6; l++) {
            int ci = tid + l * 128;
            int r = ci >> 3, kc = ci & 7;
            CP16(bB + r * 128 + ((kc ^ (r & 7)) << 4),
                 bgbase + (size_t)r * GK + kc * 8);
        }
        CP_COMMIT();
    }

#pragma unroll 1
    for (int c = 0; c < CHUNKS; c++) {
        if (c + 1 < CHUNKS) {
            int cs = c + 1;
            uint32_t aB = sb + (cs & 1) * STAGE_BYTES;
            uint32_t bB = aB + A_BYTES;
#pragma unroll
            for (int l = 0; l < 8; l++) {
                int ci = tid + l * 128;
                int r = ci >> 3, kc = ci & 7;
                CP16(aB + r * 128 + ((kc ^ (r & 7)) << 4),
                     agbase + (size_t)r * GK + cs * 64 + kc * 8);
            }
#pragma unroll
            for (int l = 0; l < 6; l++) {
                int ci = tid + l * 128;
                int r = ci >> 3, kc = ci & 7;
                CP16(bB + r * 128 + ((kc ^ (r & 7)) << 4),
                     bgbase + (size_t)r * GK + cs * 64 + kc * 8);
            }
            CP_COMMIT();
            CP_WAIT(1);
        } else {
            CP_WAIT(0);
        }
        __syncthreads();

        const uint32_t aB = sb + (c & 1) * STAGE_BYTES;
        const uint32_t bB = aB + A_BYTES;

#pragma unroll
        for (int j = 0; j < 4; j++) {
            uint32_t af[4][4];
#pragma unroll
            for (int i = 0; i < 4; i++) {
                uint32_t addr = aB + a_rowoff[i]
                              + (uint32_t)(((j * 2 + subh) ^ a_rx[i]) << 4);
                ldm_x4(af[i][0], af[i][1], af[i][2], af[i][3], addr);
            }
            uint32_t bf[6][2];
#pragma unroll
            for (int g = 0; g < 3; g++) {
                uint32_t r0, r1, r2, r3;
                uint32_t addr = bB + b_rowoff[g]
                              + (uint32_t)(((j * 2 + subh) ^ b_rx[g]) << 4);
                ldm_x4(r0, r1, r2, r3, addr);
                bf[2 * g][0]     = r0; bf[2 * g][1]     = r2;
                bf[2 * g + 1][0] = r1; bf[2 * g + 1][1] = r3;
            }
#pragma unroll
            for (int i = 0; i < 4; i++)
#pragma unroll
                for (int n = 0; n < 6; n++)
                    mma_f16(acc[i][n], af[i], bf[n][0], bf[n][1]);
        }
        __syncthreads();
    }

    // ---- epilogue: smem transpose + coalesced stores ------------------------
    __half* ep = (__half*)smem;
    const int rbase = lane >> 2;
    const int cpair = lane & 3;
#pragma unroll
    for (int i = 0; i < 4; i++) {
#pragma unroll
        for (int half = 0; half < 2; half++) {
            int row = wm * 64 + i * 16 + rbase + half * 8;
#pragma unroll
            for (int n = 0; n < 6; n++) {
                int lc0 = wn * 48 + n * 8 + cpair * 2;
                float v0 = acc[i][n][half * 2]     + __ldg(&bias[h0 * 96 + lc0]);
                float v1 = acc[i][n][half * 2 + 1] + __ldg(&bias[h0 * 96 + lc0 + 1]);
                if (lc0 % 3 == 0)       v0 *= SCALE;
                if ((lc0 + 1) % 3 == 0) v1 *= SCALE;
                *(__half2*)&ep[row * EP_PAD + lc0] = __floats2half2_rn(v0, v1);
            }
        }
    }
    __syncthreads();

#pragma unroll
    for (int l = 0; l < 12; l++) {
        int ci    = tid + l * 128;
        int chunk = ci & 3;
        int rs    = ci >> 2;
        int row   = rs & 127;
        int s     = rs >> 7;
        int m   = m0 + row;
        int b   = m / NTOK;
        int tok = m - b * NTOK;
        size_t dst = ((size_t)b * NHEAD + h0) * NTOK * HD + (size_t)tok * HD
                   + chunk * 8;
        __half tmp[8];
#pragma unroll
        for (int d8 = 0; d8 < 8; d8++)
            tmp[d8] = ep[row * EP_PAD + s + 3 * (chunk * 8 + d8)];
        __half* base = (s == 0) ? g_qh : (s == 1) ? g_kh : g_vh;
        *(uint4*)(base + dst) = *(uint4*)tmp;
    }
}

// ---------------- tensor-core attention -------------------------------------
// CTA = (h, b-pair). 4 warps, 2 window buffers, cp.async prefetch overlap.

#define RSTR 40   // halfs per row (80 bytes)
#define WBUF (112 * RSTR)

__global__ __launch_bounds__(128) void attn_tc(float* __restrict__ out)
{
    __shared__ __align__(16) __half sQ[2][WBUF];
    __shared__ __align__(16) __half sK[2][WBUF];
    __shared__ __align__(16) __half sV[2][WBUF];

    const int h    = blockIdx.x;
    const int b0   = blockIdx.y * 2;
    const int tid  = threadIdx.x;
    const int lane = tid & 31;
    const int w    = tid >> 5;
    const int g    = lane >> 2;
    const int t    = lane & 3;

    // zero pad rows 98..111 of both buffers
    for (int idx = tid; idx < 14 * 4 * 2; idx += 128) {
        int bf  = idx >= 14 * 4;
        int ix  = idx - bf * 14 * 4;
        int row = 98 + (ix >> 2);
        int q   = ix & 3;
        uint4 z = {0, 0, 0, 0};
        *(uint4*)((char*)sQ[bf] + row * 80 + q * 16) = z;
        *(uint4*)((char*)sK[bf] + row * 80 + q * 16) = z;
        *(uint4*)((char*)sV[bf] + row * 80 + q * 16) = z;
    }

    // stage both windows (separate commit groups)
#pragma unroll
    for (int bf = 0; bf < 2; bf++) {
        const size_t gbase = ((size_t)(b0 + bf) * NHEAD + h) * NTOK * HD;
        const uint32_t qB = smem_u32(sQ[bf]);
        const uint32_t kB = smem_u32(sK[bf]);
        const uint32_t vB = smem_u32(sV[bf]);
        for (int idx = tid; idx < 98 * 4; idx += 128) {
            int row = idx >> 2;
            int q   = idx & 3;
            size_t src = gbase + row * 32 + q * 8;
            uint32_t doff = row * 80 + q * 16;
            CP16(qB + doff, g_qh + src);
            CP16(kB + doff, g_kh + src);
            CP16(vB + doff, g_vh + src);
        }
        CP_COMMIT();
    }

#pragma unroll 1
    for (int bf = 0; bf < 2; bf++) {
        if (bf == 0) { CP_WAIT(1); } else { CP_WAIT(0); }
        __syncthreads();

        const int b = b0 + bf;
        const uint32_t qhB = smem_u32(sQ[bf]);
        const uint32_t khB = smem_u32(sK[bf]);
        const uint32_t vhB = smem_u32(sV[bf]);
        const float* cmbw = g_cmb + ((size_t)(b & (NWIN - 1)) * NHEAD + h) * NN;

#pragma unroll 1
        for (int mi = 0; mi < 2; mi++) {
            int mt = w + mi * 4;
            if (mt > 6) break;
            const int r0 = mt * 16;

            uint32_t qh[2][4];
            {
                int qrow = r0 + (lane & 7) + (((lane >> 3) & 1) << 3);
                int qcol = ((lane >> 4) << 3);
#pragma unroll
                for (int kt = 0; kt < 2; kt++) {
                    uint32_t off = (uint32_t)qrow * 80 + (uint32_t)(kt * 16 + qcol) * 2;
                    ldm_x4(qh[kt][0], qh[kt][1], qh[kt][2], qh[kt][3], qhB + off);
                }
            }

            float sc[14][4];
#pragma unroll
            for (int i = 0; i < 14; i++)
#pragma unroll
                for (int q = 0; q < 4; q++) sc[i][q] = 0.0f;

            {
                int krow = (lane & 7) + ((lane >> 4) << 3);
                int kcol = ((lane >> 3) & 1) << 3;
#pragma unroll
                for (int nt2 = 0; nt2 < 7; nt2++) {
                    int j0 = nt2 * 16;
                    uint32_t k0[4], k1[4];
                    uint32_t roff = (uint32_t)(j0 + krow) * 80;
                    ldm_x4(k0[0], k0[1], k0[2], k0[3], khB + roff + (uint32_t)(kcol) * 2);
                    ldm_x4(k1[0], k1[1], k1[2], k1[3], khB + roff + (uint32_t)(16 + kcol) * 2);
                    float* aA = sc[2 * nt2];
                    float* aB = sc[2 * nt2 + 1];
                    mma_f16(aA, qh[0], k0[0], k0[1]);
                    mma_f16(aA, qh[1], k1[0], k1[1]);
                    mma_f16(aB, qh[0], k0[2], k0[3]);
                    mma_f16(aB, qh[1], k1[2], k1[3]);
                }
            }

#pragma unroll
            for (int h2 = 0; h2 < 2; h2++) {
                int row = r0 + g + h2 * 8;
                float mx = -1e30f;
                bool rok = (row < NTOK);
#pragma unroll
                for (int i = 0; i < 14; i++) {
                    int jc = 8 * i + 2 * t;
                    float s0, s1;
                    if (rok && jc < NTOK) {
                        float2 cb = *(const float2*)(cmbw + row * NTOK + jc);
                        s0 = sc[i][h2 * 2]     + cb.x;
                        s1 = sc[i][h2 * 2 + 1] + cb.y;
                    } else {
                        s0 = -1e30f; s1 = -1e30f;
                    }
                    sc[i][h2 * 2]     = s0;
                    sc[i][h2 * 2 + 1] = s1;
                    mx = fmaxf(mx, fmaxf(s0, s1));
                }
                mx = fmaxf(mx, __shfl_xor_sync(0xffffffffu, mx, 1));
                mx = fmaxf(mx, __shfl_xor_sync(0xffffffffu, mx, 2));
                float sum = 0.0f;
#pragma unroll
                for (int i = 0; i < 14; i++) {
                    float p0 = __expf(sc[i][h2 * 2]     - mx);
                    float p1 = __expf(sc[i][h2 * 2 + 1] - mx);
                    sc[i][h2 * 2]     = p0;
                    sc[i][h2 * 2 + 1] = p1;
                    sum += p0 + p1;
                }
                sum += __shfl_xor_sync(0xffffffffu, sum, 1);
                sum += __shfl_xor_sync(0xffffffffu, sum, 2);
                float inv = 1.0f / sum;
#pragma unroll
                for (int i = 0; i < 14; i++) {
                    sc[i][h2 * 2]     *= inv;
                    sc[i][h2 * 2 + 1] *= inv;
                }
            }

            float o[4][4];
#pragma unroll
            for (int n = 0; n < 4; n++)
#pragma unroll
                for (int q = 0; q < 4; q++) o[n][q] = 0.0f;

            {
                int vrow = (lane & 7) + (((lane >> 3) & 1) << 3);
                int vcol = (lane >> 4) << 3;
#pragma unroll
                for (int kk = 0; kk < 7; kk++) {
                    uint32_t ph[4];
                    {
                        __half2 p0 = __floats2half2_rn(sc[2 * kk][0],     sc[2 * kk][1]);
                        __half2 p1 = __floats2half2_rn(sc[2 * kk][2],     sc[2 * kk][3]);
                        __half2 p2 = __floats2half2_rn(sc[2 * kk + 1][0], sc[2 * kk + 1][1]);
                        __half2 p3 = __floats2half2_rn(sc[2 * kk + 1][2], sc[2 * kk + 1][3]);
                        ph[0] = *(uint32_t*)&p0;
                        ph[1] = *(uint32_t*)&p1;
                        ph[2] = *(uint32_t*)&p2;
                        ph[3] = *(uint32_t*)&p3;
                    }
                    int j0 = kk * 16;
                    uint32_t v0[4], v16[4];
                    uint32_t roff = (uint32_t)(j0 + vrow) * 80;
                    ldm_x4_t(v0[0], v0[1], v0[2], v0[3],  vhB + roff + (uint32_t)vcol * 2);
                    ldm_x4_t(v16[0], v16[1], v16[2], v16[3],
                             vhB + roff + (uint32_t)(16 + vcol) * 2);
                    mma_f16(o[0], ph, v0[0], v0[1]);
                    mma_f16(o[1], ph, v0[2], v0[3]);
                    mma_f16(o[2], ph, v16[0], v16[1]);
                    mma_f16(o[3], ph, v16[2], v16[3]);
                }
            }

            {
                int rowA = r0 + g;
                int rowB = rowA + 8;
                if (rowA < NTOK) {
                    float* dst = out + ((size_t)b * NTOK + rowA) * DIMC + h * HD;
#pragma unroll
                    for (int n = 0; n < 4; n++) {
                        float2 v = {o[n][0], o[n][1]};
                        *(float2*)(dst + n * 8 + 2 * t) = v;
                    }
                }
                if (rowB < NTOK) {
                    float* dst = out + ((size_t)b * NTOK + rowB) * DIMC + h * HD;
#pragma unroll
                    for (int n = 0; n < 4; n++) {
                        float2 v = {o[n][2], o[n][3]};
                        *(float2*)(dst + n * 8 + 2 * t) = v;
                    }
                }
            }
        }
    }
}

// ------------------------- launch ------------------------------------------

extern "C" void kernel_launch(void* const* d_in, const int* in_sizes, int n_in,
                              void* d_out, int out_size)
{
    const float* x         = (const float*)d_in[0];
    const float* mask      = (const float*)d_in[1];
    const float* qkv_w     = (const float*)d_in[2];
    const float* qkv_b     = (const float*)d_in[3];
    const float* rel_table = (const float*)d_in[4];
    const int*   rel_index = (const int*)  d_in[5];
    float* out = (float*)d_out;

    prep_all<<<(NTOT4 + 255) / 256, 256>>>(x, qkv_w, mask, rel_table, rel_index);

    cudaFuncSetAttribute(qkv_mma, cudaFuncAttributeMaxDynamicSharedMemorySize,
                         SMEM_TOTAL);
    dim3 g1(NHEAD, GM / 128);       // (24, 196)
    qkv_mma<<<g1, 128, SMEM_TOTAL>>>(qkv_b);

    dim3 g2(NHEAD, B_ / 2);         // (24, 128) — 2 windows per CTA
    attn_tc<<<g2, 128>>>(out);
}